// round 13
// baseline (speedup 1.0000x reference)
#include <cuda_runtime.h>
#include <math.h>
#include <stdint.h>

#define B 4
#define T 1024
#define D 1024
#define H 16
#define DH 64
#define FFN 4096
#define KSEL 256
#define EPSV 1e-6f
#define CVARF 1.0f
#define LOGCF 0.0f
#define BCE 1.0f
#define BCU 1.0f
#define NEGINF (-1.0e30f)
#define DD (D*D)

// ------------------------------- scratch (device globals; no allocation) ----
__device__ float g_h   [B*T*D];
__device__ float g_q   [B*T*D];
__device__ float g_k   [B*T*D];
__device__ float g_v   [B*T*D];
__device__ float g_attn[B*T*D];
__device__ float g_x   [B*T*D];
__device__ float g_ffg [B*T*FFN];
__device__ float g_ffu [B*T*FFN];
__device__ float g_mulv[B*T*2*D];
__device__ float g_dst [B*T];
__device__ float g_dch [B*T];
__device__ float g_gate[B*T];
__device__ float g_means[2];
__device__ int   g_idx [B*KSEL];
__device__ float g_sc  [B*KSEL];
__device__ float g_sel [B*KSEL*D];
__device__ float g_y   [B*KSEL*D];
// tf32-pre-rounded weights: 8 DxD + 1 Dx2D + 6 DxFFN
__device__ float g_wbuf[(size_t)10*DD + (size_t)6*D*FFN];

// ------------------------------- reductions --------------------------------
__device__ __forceinline__ float blockReduceSum(float v) {
    __shared__ float sh[32];
    int lane = threadIdx.x & 31, wid = threadIdx.x >> 5;
    #pragma unroll
    for (int o = 16; o > 0; o >>= 1) v += __shfl_xor_sync(0xffffffffu, v, o);
    if (lane == 0) sh[wid] = v;
    __syncthreads();
    int nw = (blockDim.x + 31) >> 5;
    float t = (threadIdx.x < nw) ? sh[threadIdx.x] : 0.f;
    if (wid == 0) {
        #pragma unroll
        for (int o = 16; o > 0; o >>= 1) t += __shfl_xor_sync(0xffffffffu, t, o);
        if (lane == 0) sh[0] = t;
    }
    __syncthreads();
    float r = sh[0];
    __syncthreads();
    return r;
}

// ------------------------------- tf32 helpers ------------------------------
__device__ __forceinline__ float f2tf32(float x) {
    uint32_t r;
    asm("cvt.rna.tf32.f32 %0, %1;" : "=r"(r) : "f"(x));
    return __uint_as_float(r);
}

__device__ __forceinline__ void mma_tf32(float c[4], const uint32_t a[4], const uint32_t b[2]) {
    asm volatile(
        "mma.sync.aligned.m16n8k8.row.col.f32.tf32.tf32.f32 "
        "{%0,%1,%2,%3}, {%4,%5,%6,%7}, {%8,%9}, {%0,%1,%2,%3};"
        : "+f"(c[0]), "+f"(c[1]), "+f"(c[2]), "+f"(c[3])
        : "r"(a[0]), "r"(a[1]), "r"(a[2]), "r"(a[3]), "r"(b[0]), "r"(b[1]));
}

__device__ __forceinline__ void cp16(uint32_t s, const float* g) {
    asm volatile("cp.async.cg.shared.global [%0], [%1], 16;" :: "r"(s), "l"(g));
}
__device__ __forceinline__ void cp_commit() { asm volatile("cp.async.commit_group;"); }
__device__ __forceinline__ void cp_wait0()  { asm volatile("cp.async.wait_group 0;"); }
__device__ __forceinline__ void cp_wait1()  { asm volatile("cp.async.wait_group 1;"); }

// ------------------------------- elementwise tf32 convert ------------------
__global__ void cvt_tf32_k(const float* __restrict__ in, float* __restrict__ out, int n4) {
    int i = blockIdx.x * blockDim.x + threadIdx.x;
    if (i >= n4) return;
    float4 v = ((const float4*)in)[i];
    v.x = f2tf32(v.x); v.y = f2tf32(v.y); v.z = f2tf32(v.z); v.w = f2tf32(v.w);
    ((float4*)out)[i] = v;
}

// ------------------------------- rmsnorm (output tf32-rounded) -------------
__global__ void rmsnorm_k(const float* __restrict__ x, const float* __restrict__ w,
                          float* __restrict__ o) {
    size_t row = blockIdx.x;
    const float4* xr = (const float4*)(x + row * D);
    float4 xv = xr[threadIdx.x];
    float ss = xv.x*xv.x + xv.y*xv.y + xv.z*xv.z + xv.w*xv.w;
    ss = blockReduceSum(ss);
    float rs = rsqrtf(ss / (float)D + EPSV);
    float4 wv = ((const float4*)w)[threadIdx.x];
    float4 ov = make_float4(f2tf32(xv.x*rs*wv.x), f2tf32(xv.y*rs*wv.y),
                            f2tf32(xv.z*rs*wv.z), f2tf32(xv.w*rs*wv.w));
    ((float4*)(o + row * D))[threadIdx.x] = ov;
}

// ------------------------------- GEMM tf32 (BM=64, BN=64, high-occ) --------
// C[M,N] = A[M,K] @ Bm[K,N] (+ C0). Inputs tf32-pre-rounded.
// 128 thr = 4 warps (2m x 2n), warp tile 32x32, mma m16n8k8, cp.async 2-stage.
// Small CTA -> ~6 CTAs/SM resident: latency-bound regime gets 1.5x warps/SMSP.
__global__ __launch_bounds__(128, 6)
void gemm_tf32(const float* __restrict__ A, const float* __restrict__ Bm,
               const float* __restrict__ C0, float* __restrict__ C,
               int M, int N, int K)
{
    __shared__ float As[2][64][20];   // [buf][m][k] pad 4
    __shared__ float Bs[2][16][72];   // [buf][k][n] pad 8

    const int tid = threadIdx.x;
    const int warp = tid >> 5, lane = tid & 31;
    const int gid = lane >> 2, tig = lane & 3;
    const int wm = (warp & 1) * 32;
    const int wn = (warp >> 1) * 32;
    const int rowBase = blockIdx.y * 64;
    const int colBase = blockIdx.x * 64;

    const int aRow = tid >> 2;            // 0..31 (+32)
    const int aCol = (tid & 3) << 2;      // 0,4,8,12
    const int bRow = tid >> 4;            // 0..7 (+8)
    const int bCol = (tid & 15) << 2;     // 0..60

    const float* Ap = A + (size_t)(rowBase + aRow) * K + aCol;
    const float* Bp = Bm + (size_t)bRow * N + colBase + bCol;

    const uint32_t sA0 = (uint32_t)__cvta_generic_to_shared(&As[0][aRow][aCol]);
    const uint32_t sA1 = (uint32_t)__cvta_generic_to_shared(&As[0][aRow + 32][aCol]);
    const uint32_t sB0 = (uint32_t)__cvta_generic_to_shared(&Bs[0][bRow][bCol]);
    const uint32_t sB1 = (uint32_t)__cvta_generic_to_shared(&Bs[0][bRow + 8][bCol]);
    const uint32_t dAbuf = 64 * 20 * 4;
    const uint32_t dBbuf = 16 * 72 * 4;

    float acc[2][4][4];
    #pragma unroll
    for (int mt = 0; mt < 2; mt++)
        #pragma unroll
        for (int nt = 0; nt < 4; nt++)
            #pragma unroll
            for (int i = 0; i < 4; i++) acc[mt][nt][i] = 0.f;

    const int numT = K >> 4;

    cp16(sA0, Ap);
    cp16(sA1, Ap + (size_t)32 * K);
    cp16(sB0, Bp);
    cp16(sB1, Bp + (size_t)8 * N);
    cp_commit();

    for (int t = 0; t < numT; t++) {
        const int buf = t & 1;
        const bool hasNext = (t + 1 < numT);
        if (hasNext) {
            const int k0 = (t + 1) << 4;
            const uint32_t oA = (buf ^ 1) ? dAbuf : 0u;
            const uint32_t oB = (buf ^ 1) ? dBbuf : 0u;
            cp16(sA0 + oA, Ap + k0);
            cp16(sA1 + oA, Ap + (size_t)32 * K + k0);
            cp16(sB0 + oB, Bp + (size_t)k0 * N);
            cp16(sB1 + oB, Bp + (size_t)(k0 + 8) * N);
            cp_commit();
            cp_wait1();
        } else {
            cp_wait0();
        }
        __syncthreads();

        #pragma unroll
        for (int ks = 0; ks < 16; ks += 8) {
            const int kLo = ks + tig;
            const int kHi = kLo + 4;

            uint32_t af[2][4];
            #pragma unroll
            for (int mt = 0; mt < 2; mt++) {
                int m = wm + mt * 16 + gid;
                af[mt][0] = __float_as_uint(As[buf][m    ][kLo]);
                af[mt][1] = __float_as_uint(As[buf][m + 8][kLo]);
                af[mt][2] = __float_as_uint(As[buf][m    ][kHi]);
                af[mt][3] = __float_as_uint(As[buf][m + 8][kHi]);
            }
            uint32_t bf[4][2];
            #pragma unroll
            for (int nt = 0; nt < 4; nt++) {
                int n = wn + nt * 8 + gid;
                bf[nt][0] = __float_as_uint(Bs[buf][kLo][n]);
                bf[nt][1] = __float_as_uint(Bs[buf][kHi][n]);
            }
            #pragma unroll
            for (int mt = 0; mt < 2; mt++)
                #pragma unroll
                for (int nt = 0; nt < 4; nt++)
                    mma_tf32(acc[mt][nt], af[mt], bf[nt]);
        }
        __syncthreads();
    }

    #pragma unroll
    for (int mt = 0; mt < 2; mt++) {
        int r0 = rowBase + wm + mt * 16 + gid;
        int r1 = r0 + 8;
        #pragma unroll
        for (int nt = 0; nt < 4; nt++) {
            int c = colBase + wn + nt * 8 + tig * 2;
            size_t o0 = (size_t)r0 * N + c;
            size_t o1 = (size_t)r1 * N + c;
            float2 v0 = make_float2(acc[mt][nt][0], acc[mt][nt][1]);
            float2 v1 = make_float2(acc[mt][nt][2], acc[mt][nt][3]);
            if (C0) {
                float2 p0 = *(const float2*)(C0 + o0);
                float2 p1 = *(const float2*)(C0 + o1);
                v0.x += p0.x; v0.y += p0.y;
                v1.x += p1.x; v1.y += p1.y;
            }
            *(float2*)(C + o0) = v0;
            *(float2*)(C + o1) = v1;
        }
    }
}

static inline void launch_gemm(const float* A, const float* Bm, const float* C0,
                               float* C, int M, int N, int K)
{
    gemm_tf32<<<dim3(N / 64, M / 64), 128>>>(A, Bm, C0, C, M, N, K);
}

// ------------------------------- RoPE (in place) ---------------------------
__global__ void rope_k(float* __restrict__ x, const int* __restrict__ posIdx, int S) {
    int gid = blockIdx.x * blockDim.x + threadIdx.x;
    int total = B * S * H * (DH/2);
    if (gid >= total) return;
    int j = gid & 31;
    int h = (gid >> 5) & (H - 1);
    int sb = gid >> 9;
    int s = sb % S;
    int b = sb / S;
    float p = posIdx ? (float)posIdx[b * S + s] : (float)s;
    float inv = powf(10000.f, -(float)j / 32.f);
    float ang = p * inv;
    float c = cosf(ang), sn = sinf(ang);
    size_t base = ((size_t)(b * S + s) * H + h) * DH;
    float x1 = x[base + j], x2 = x[base + 32 + j];
    x[base + j]      = x1 * c - x2 * sn;
    x[base + 32 + j] = x2 * c + x1 * sn;
}

// ------------------------------- fused flash attention ---------------------
#define FST 68
__global__ __launch_bounds__(256)
void flash_attn(const float* __restrict__ q, const float* __restrict__ k,
                const float* __restrict__ v, const float* __restrict__ o, int S)
{
    extern __shared__ float sm[];
    float (*Qs)[FST] = (float(*)[FST])sm;
    float (*Ks)[FST] = (float(*)[FST])(sm + 64*FST);      // reused as Ps
    float (*Vt)[FST] = (float(*)[FST])(sm + 2*64*FST);    // [dh][token]
    __shared__ float redmx[2][64];
    __shared__ float redsm[2][64];

    const int bh = blockIdx.y;
    const int b = bh / H, h = bh % H;
    const int q0 = blockIdx.x * 64;
    const int tid = threadIdx.x, warp = tid >> 5, lane = tid & 31;
    const int gid = lane >> 2, tig = lane & 3;
    const int wm = (warp & 3) * 16;
    const int wn = (warp >> 2) * 32;
    const int warp_n = warp >> 2;

    #pragma unroll
    for (int i = 0; i < 4; i++) {
        int f4 = tid + i * 256;
        int r = f4 >> 4, c = (f4 & 15) << 2;
        float4 qv = *(const float4*)(q + ((size_t)(b*S + q0 + r)) * (H*DH) + h*DH + c);
        Qs[r][c+0] = f2tf32(qv.x); Qs[r][c+1] = f2tf32(qv.y);
        Qs[r][c+2] = f2tf32(qv.z); Qs[r][c+3] = f2tf32(qv.w);
    }

    float mI[2] = {NEGINF, NEGINF};
    float lI[2] = {0.f, 0.f};
    float oacc[4][4];
    #pragma unroll
    for (int nt = 0; nt < 4; nt++)
        #pragma unroll
        for (int r = 0; r < 4; r++) oacc[nt][r] = 0.f;

    const int numKT = blockIdx.x + 1;
    for (int kt = 0; kt < numKT; kt++) {
        const int k0 = kt * 64;
        __syncthreads();
        #pragma unroll
        for (int i = 0; i < 4; i++) {
            int f4 = tid + i * 256;
            int r = f4 >> 4, c = (f4 & 15) << 2;
            size_t gbase = ((size_t)(b*S + k0 + r)) * (H*DH) + h*DH + c;
            float4 kv = *(const float4*)(k + gbase);
            Ks[r][c+0] = f2tf32(kv.x); Ks[r][c+1] = f2tf32(kv.y);
            Ks[r][c+2] = f2tf32(kv.z); Ks[r][c+3] = f2tf32(kv.w);
            float4 vv = *(const float4*)(v + gbase);
            Vt[c+0][r] = f2tf32(vv.x); Vt[c+1][r] = f2tf32(vv.y);
            Vt[c+2][r] = f2tf32(vv.z); Vt[c+3][r] = f2tf32(vv.w);
        }
        __syncthreads();

        float sacc[4][4];
        #pragma unroll
        for (int nt = 0; nt < 4; nt++)
            #pragma unroll
            for (int r = 0; r < 4; r++) sacc[nt][r] = 0.f;

        #pragma unroll
        for (int ks = 0; ks < 64; ks += 8) {
            const int kLo = ks + tig, kHi = kLo + 4;
            uint32_t af[4];
            af[0] = __float_as_uint(Qs[wm + gid    ][kLo]);
            af[1] = __float_as_uint(Qs[wm + gid + 8][kLo]);
            af[2] = __float_as_uint(Qs[wm + gid    ][kHi]);
            af[3] = __float_as_uint(Qs[wm + gid + 8][kHi]);
            #pragma unroll
            for (int nt = 0; nt < 4; nt++) {
                uint32_t bf[2];
                bf[0] = __float_as_uint(Ks[wn + nt*8 + gid][kLo]);
                bf[1] = __float_as_uint(Ks[wn + nt*8 + gid][kHi]);
                mma_tf32(sacc[nt], af, bf);
            }
        }

        const float scale = 0.125f;
        const bool diag = (kt == numKT - 1);
        #pragma unroll
        for (int nt = 0; nt < 4; nt++)
            #pragma unroll
            for (int r = 0; r < 4; r++) {
                int rowg = q0 + wm + gid + ((r >> 1) << 3);
                int colg = k0 + wn + nt*8 + tig*2 + (r & 1);
                float sv = sacc[nt][r] * scale;
                sacc[nt][r] = (diag && colg > rowg) ? NEGINF : sv;
            }

        float rmx[2];
        #pragma unroll
        for (int j = 0; j < 2; j++) {
            float m0 = fmaxf(sacc[0][2*j], sacc[0][2*j+1]);
            #pragma unroll
            for (int nt = 1; nt < 4; nt++)
                m0 = fmaxf(m0, fmaxf(sacc[nt][2*j], sacc[nt][2*j+1]));
            m0 = fmaxf(m0, __shfl_xor_sync(0xffffffffu, m0, 1));
            m0 = fmaxf(m0, __shfl_xor_sync(0xffffffffu, m0, 2));
            rmx[j] = m0;
        }
        if (tig == 0) {
            redmx[warp_n][wm + gid    ] = rmx[0];
            redmx[warp_n][wm + gid + 8] = rmx[1];
        }
        __syncthreads();
        rmx[0] = fmaxf(redmx[0][wm + gid    ], redmx[1][wm + gid    ]);
        rmx[1] = fmaxf(redmx[0][wm + gid + 8], redmx[1][wm + gid + 8]);

        float mnew[2], alpha[2];
        #pragma unroll
        for (int j = 0; j < 2; j++) {
            mnew[j] = fmaxf(mI[j], rmx[j]);
            alpha[j] = expf(mI[j] - mnew[j]);
            mI[j] = mnew[j];
        }

        float rsum[2] = {0.f, 0.f};
        #pragma unroll
        for (int nt = 0; nt < 4; nt++)
            #pragma unroll
            for (int r = 0; r < 4; r++) {
                int j = r >> 1;
                float p = expf(sacc[nt][r] - mnew[j]);
                rsum[j] += p;
                Ks[wm + gid + (j << 3)][wn + nt*8 + tig*2 + (r & 1)] = f2tf32(p);
            }
        #pragma unroll
        for (int j = 0; j < 2; j++) {
            rsum[j] += __shfl_xor_sync(0xffffffffu, rsum[j], 1);
            rsum[j] += __shfl_xor_sync(0xffffffffu, rsum[j], 2);
        }
        if (tig == 0) {
            redsm[warp_n][wm + gid    ] = rsum[0];
            redsm[warp_n][wm + gid + 8] = rsum[1];
        }
        __syncthreads();
        rsum[0] = redsm[0][wm + gid    ] + redsm[1][wm + gid    ];
        rsum[1] = redsm[0][wm + gid + 8] + redsm[1][wm + gid + 8];

        #pragma unroll
        for (int j = 0; j < 2; j++) lI[j] = alpha[j] * lI[j] + rsum[j];
        #pragma unroll
        for (int nt = 0; nt < 4; nt++) {
            oacc[nt][0] *= alpha[0]; oacc[nt][1] *= alpha[0];
            oacc[nt][2] *= alpha[1]; oacc[nt][3] *= alpha[1];
        }

        #pragma unroll
        for (int ks = 0; ks < 64; ks += 8) {
            const int kLo = ks + tig, kHi = kLo + 4;
            uint32_t af[4];
            af[0] = __float_as_uint(Ks[wm + gid    ][kLo]);
            af[1] = __float_as_uint(Ks[wm + gid + 8][kLo]);
            af[2] = __float_as_uint(Ks[wm + gid    ][kHi]);
            af[3] = __float_as_uint(Ks[wm + gid + 8][kHi]);
            #pragma unroll
            for (int nt = 0; nt < 4; nt++) {
                uint32_t bf[2];
                bf[0] = __float_as_uint(Vt[wn + nt*8 + gid][kLo]);
                bf[1] = __float_as_uint(Vt[wn + nt*8 + gid][kHi]);
                mma_tf32(oacc[nt], af, bf);
            }
        }
    }

    float inv0 = 1.f / lI[0], inv1 = 1.f / lI[1];
    float* op = (float*)o;
    #pragma unroll
    for (int nt = 0; nt < 4; nt++) {
        int col = h*DH + wn + nt*8 + tig*2;
        size_t r0 = ((size_t)(b*S + q0 + wm + gid)) * (H*DH) + col;
        size_t r1 = ((size_t)(b*S + q0 + wm + gid + 8)) * (H*DH) + col;
        *(float2*)(op + r0) = make_float2(f2tf32(oacc[nt][0]*inv0), f2tf32(oacc[nt][1]*inv0));
        *(float2*)(op + r1) = make_float2(f2tf32(oacc[nt][2]*inv1), f2tf32(oacc[nt][3]*inv1));
    }
}

// ------------------------------- SwiGLU (output tf32-rounded) --------------
__global__ void silu_mul_k(float* __restrict__ g, const float* __restrict__ u, int n4) {
    int i = blockIdx.x * blockDim.x + threadIdx.x;
    if (i >= n4) return;
    float4 gv = ((const float4*)g)[i];
    float4 uv = ((const float4*)u)[i];
    gv.x = f2tf32(gv.x / (1.f + expf(-gv.x)) * uv.x);
    gv.y = f2tf32(gv.y / (1.f + expf(-gv.y)) * uv.y);
    gv.z = f2tf32(gv.z / (1.f + expf(-gv.z)) * uv.z);
    gv.w = f2tf32(gv.w / (1.f + expf(-gv.w)) * uv.w);
    ((float4*)g)[i] = gv;
}

// ------------------------------- router ------------------------------------
__global__ void router_stats(const float* __restrict__ proc, const float* __restrict__ hid,
                             const float* __restrict__ mulv,
                             float* __restrict__ dst, float* __restrict__ dch)
{
    size_t row = blockIdx.x;
    const float* pr = proc + row * D;
    const float* hi = hid + row * D;
    const float* mu = mulv + row * (2 * D);
    const float* lv = mu + D;
    float s1 = 0.f, s2 = 0.f;
    for (int i = threadIdx.x; i < D; i += 256) {
        float r = pr[i] - hi[i];
        s1 += r * r;
        float l = lv[i];
        float dm = r - mu[i];
        s2 += 0.5f * (l - LOGCF + (CVARF + dm * dm) * expf(-l) - 1.0f);
    }
    s1 = blockReduceSum(s1);
    s2 = blockReduceSum(s2);
    if (threadIdx.x == 0) {
        dst[row] = s1 / (float)D;
        dch[row] = s2 / (float)D;
    }
}

__global__ void router_means(const float* __restrict__ dst, const float* __restrict__ dch,
                             float* __restrict__ means)
{
    float s1 = 0.f, s2 = 0.f;
    for (int i = threadIdx.x; i < B * T; i += 1024) { s1 += dst[i]; s2 += dch[i]; }
    s1 = blockReduceSum(s1);
    s2 = blockReduceSum(s2);
    if (threadIdx.x == 0) {
        means[0] = s1 / (float)(B * T);
        means[1] = s2 / (float)(B * T);
    }
}

__global__ void router_gate(const float* __restrict__ dst, const float* __restrict__ dch,
                            const float* __restrict__ means, float* __restrict__ g)
{
    int i = blockIdx.x * blockDim.x + threadIdx.x;
    if (i >= B * T) return;
    float z = BCE * (dst[i] - means[0]) + BCU * (dch[i] - means[1]);
    g[i] = 1.f / (1.f + expf(-z));
}

__global__ void topk_k(const float* __restrict__ g, int* __restrict__ idxO,
                       float* __restrict__ scO)
{
    int b = blockIdx.x;
    int i = threadIdx.x;
    __shared__ float gs[T];
    __shared__ unsigned char flag[T];
    gs[i] = g[b * T + i];
    __syncthreads();
    float gi = gs[i];
    int rank = 0;
    for (int j = 0; j < T; j++) {
        float gj = gs[j];
        rank += (gj > gi) || (gj == gi && j < i);
    }
    flag[i] = (rank < KSEL) ? 1 : 0;
    __syncthreads();
    if (flag[i]) {
        int pos = 0;
        for (int j = 0; j < i; j++) pos += flag[j];
        idxO[b * KSEL + pos] = i;
        scO[b * KSEL + pos] = gi;
    }
}

// ------------------------------- gather / scatter --------------------------
__global__ void gather_k(const float* __restrict__ proc, const int* __restrict__ idx,
                         float* __restrict__ sel)
{
    int row = blockIdx.x;
    int b = row / KSEL;
    int src = idx[row];
    const float4* s4 = (const float4*)(proc + ((size_t)b * T + src) * D);
    float4* d4 = (float4*)(sel + (size_t)row * D);
    d4[threadIdx.x] = s4[threadIdx.x];
}

__global__ void scatter_k(const float* __restrict__ sel, const float* __restrict__ y,
                          const float* __restrict__ sc, const int* __restrict__ idx,
                          float* __restrict__ out)
{
    int row = blockIdx.x;
    int b = row / KSEL;
    float s = sc[row];
    size_t drow = ((size_t)b * T + idx[row]) * D;
    const float4* s4 = (const float4*)(sel + (size_t)row * D);
    const float4* y4 = (const float4*)(y + (size_t)row * D);
    float4 sv = s4[threadIdx.x];
    float4 yv = y4[threadIdx.x];
    float4 ov = make_float4(sv.x + s * (yv.x - sv.x),
                            sv.y + s * (yv.y - sv.y),
                            sv.z + s * (yv.z - sv.z),
                            sv.w + s * (yv.w - sv.w));
    ((float4*)(out + drow))[threadIdx.x] = ov;
}

// ------------------------------- host: decoder pipeline --------------------
#define FLASH_SMEM (3 * 64 * FST * 4)

static void run_decoder(const float* x_in, int S, const int* posIdx,
                        const float* ln1, const float* wq, const float* wk,
                        const float* wv, const float* wo, const float* ln2,
                        const float* wg, const float* wu, const float* wd,
                        float* out,
                        float* h, float* q, float* k, float* v, float* attn,
                        float* x, float* ffg, float* ffu)
{
    const int M = B * S;
    rmsnorm_k<<<M, 256>>>(x_in, ln1, h);
    launch_gemm(h, wq, nullptr, q, M, D, D);
    launch_gemm(h, wk, nullptr, k, M, D, D);
    launch_gemm(h, wv, nullptr, v, M, D, D);
    int ropeTotal = B * S * H * (DH / 2);
    rope_k<<<(ropeTotal + 255) / 256, 256>>>(q, posIdx, S);
    rope_k<<<(ropeTotal + 255) / 256, 256>>>(k, posIdx, S);
    flash_attn<<<dim3(S / 64, B * H), 256, FLASH_SMEM>>>(q, k, v, attn, S);
    launch_gemm(attn, wo, x_in, x, M, D, D);
    rmsnorm_k<<<M, 256>>>(x, ln2, h);
    launch_gemm(h, wg, nullptr, ffg, M, FFN, D);
    launch_gemm(h, wu, nullptr, ffu, M, FFN, D);
    int n4 = M * FFN / 4;
    silu_mul_k<<<(n4 + 255) / 256, 256>>>(ffg, ffu, n4);
    launch_gemm(ffg, wd, x, out, M, D, FFN);
}

// ------------------------------- entry -------------------------------------
extern "C" void kernel_launch(void* const* d_in, const int* in_sizes, int n_in,
                              void* d_out, int out_size)
{
    if (n_in < 21) return;
    const float* in[21];
    for (int i = 0; i < 21; i++) in[i] = (const float*)d_in[i];

    const float *hidden, *ln1_1, *wq1, *wk1, *wv1, *wo1, *ln2_1, *wg1, *wu1, *wd1;
    const float *ln1_2, *wq2, *wk2, *wv2, *wo2, *ln2_2, *wg2, *wu2, *wd2, *pnw, *pw;

    if (in_sizes[1] == D) {
        hidden = in[0];  ln1_1 = in[1];  wq1 = in[2];  wk1 = in[3];  wv1 = in[4];
        wo1 = in[5];     ln2_1 = in[6];  wg1 = in[7];  wu1 = in[8];  wd1 = in[9];
        ln1_2 = in[10];  wq2 = in[11];   wk2 = in[12]; wv2 = in[13]; wo2 = in[14];
        ln2_2 = in[15];  wg2 = in[16];   wu2 = in[17]; wd2 = in[18];
        pnw = in[19];    pw = in[20];
    } else {
        hidden = in[0];
        wq1 = in[1];  wk1 = in[2];  wv1 = in[3];  wo1 = in[4];
        wq2 = in[5];  wk2 = in[6];  wv2 = in[7];  wo2 = in[8];
        wg1 = in[9];  wu1 = in[10]; wd1 = in[11];
        wg2 = in[12]; wu2 = in[13]; wd2 = in[14];
        ln1_1 = in[15]; ln2_1 = in[16]; ln1_2 = in[17]; ln2_2 = in[18];
        pnw = in[19]; pw = in[20];
    }

    cudaFuncSetAttribute(flash_attn, cudaFuncAttributeMaxDynamicSharedMemorySize,
                         FLASH_SMEM);

    float *h, *q, *k, *v, *attn, *x, *ffg, *ffu, *mulv;
    float *dst, *dch, *gate, *means, *sc, *sel, *y, *wbuf;
    int* idx;
    cudaGetSymbolAddress((void**)&h, g_h);
    cudaGetSymbolAddress((void**)&q, g_q);
    cudaGetSymbolAddress((void**)&k, g_k);
    cudaGetSymbolAddress((void**)&v, g_v);
    cudaGetSymbolAddress((void**)&attn, g_attn);
    cudaGetSymbolAddress((void**)&x, g_x);
    cudaGetSymbolAddress((void**)&ffg, g_ffg);
    cudaGetSymbolAddress((void**)&ffu, g_ffu);
    cudaGetSymbolAddress((void**)&mulv, g_mulv);
    cudaGetSymbolAddress((void**)&dst, g_dst);
    cudaGetSymbolAddress((void**)&dch, g_dch);
    cudaGetSymbolAddress((void**)&gate, g_gate);
    cudaGetSymbolAddress((void**)&means, g_means);
    cudaGetSymbolAddress((void**)&idx, g_idx);
    cudaGetSymbolAddress((void**)&sc, g_sc);
    cudaGetSymbolAddress((void**)&sel, g_sel);
    cudaGetSymbolAddress((void**)&y, g_y);
    cudaGetSymbolAddress((void**)&wbuf, g_wbuf);

    // pre-round weights to tf32 (scratch copies)
    float* cwq1 = wbuf + (size_t)0 * DD;
    float* cwk1 = wbuf + (size_t)1 * DD;
    float* cwv1 = wbuf + (size_t)2 * DD;
    float* cwo1 = wbuf + (size_t)3 * DD;
    float* cwq2 = wbuf + (size_t)4 * DD;
    float* cwk2 = wbuf + (size_t)5 * DD;
    float* cwv2 = wbuf + (size_t)6 * DD;
    float* cwo2 = wbuf + (size_t)7 * DD;
    float* cpw  = wbuf + (size_t)8 * DD;                    // D x 2D
    float* cwg1 = wbuf + (size_t)10 * DD;
    float* cwu1 = cwg1 + (size_t)D * FFN;
    float* cwd1 = cwu1 + (size_t)D * FFN;
    float* cwg2 = cwd1 + (size_t)D * FFN;
    float* cwu2 = cwg2 + (size_t)D * FFN;
    float* cwd2 = cwu2 + (size_t)D * FFN;

    const int nDD4 = DD / 4, nDF4 = D * FFN / 4, nP4 = 2 * DD / 4;
    cvt_tf32_k<<<(nDD4 + 255) / 256, 256>>>(wq1, cwq1, nDD4);
    cvt_tf32_k<<<(nDD4 + 255) / 256, 256>>>(wk1, cwk1, nDD4);
    cvt_tf32_k<<<(nDD4 + 255) / 256, 256>>>(wv1, cwv1, nDD4);
    cvt_tf32_k<<<(nDD4 + 255) / 256, 256>>>(wo1, cwo1, nDD4);
    cvt_tf32_k<<<(nDD4 + 255) / 256, 256>>>(wq2, cwq2, nDD4);
    cvt_tf32_k<<<(nDD4 + 255) / 256, 256>>>(wk2, cwk2, nDD4);
    cvt_tf32_k<<<(nDD4 + 255) / 256, 256>>>(wv2, cwv2, nDD4);
    cvt_tf32_k<<<(nDD4 + 255) / 256, 256>>>(wo2, cwo2, nDD4);
    cvt_tf32_k<<<(nP4 + 255) / 256, 256>>>(pw, cpw, nP4);
    cvt_tf32_k<<<(nDF4 + 255) / 256, 256>>>(wg1, cwg1, nDF4);
    cvt_tf32_k<<<(nDF4 + 255) / 256, 256>>>(wu1, cwu1, nDF4);
    cvt_tf32_k<<<(nDF4 + 255) / 256, 256>>>(wd1, cwd1, nDF4);
    cvt_tf32_k<<<(nDF4 + 255) / 256, 256>>>(wg2, cwg2, nDF4);
    cvt_tf32_k<<<(nDF4 + 255) / 256, 256>>>(wu2, cwu2, nDF4);
    cvt_tf32_k<<<(nDF4 + 255) / 256, 256>>>(wd2, cwd2, nDF4);

    float* proc = (float*)d_out;   // decoder1 writes the output buffer directly

    // decoder 1: hidden -> proc (= d_out)
    run_decoder(hidden, T, nullptr,
                ln1_1, cwq1, cwk1, cwv1, cwo1, ln2_1, cwg1, cwu1, cwd1,
                proc, h, q, k, v, attn, x, ffg, ffu);

    // router
    rmsnorm_k<<<B * T, 256>>>(hidden, pnw, h);
    launch_gemm(h, cpw, nullptr, mulv, B * T, 2 * D, D);
    router_stats<<<B * T, 256>>>(proc, hidden, mulv, dst, dch);
    router_means<<<1, 1024>>>(dst, dch, means);
    router_gate<<<(B * T + 255) / 256, 256>>>(dst, dch, means, gate);
    topk_k<<<B, 1024>>>(gate, idx, sc);
    gather_k<<<B * KSEL, 256>>>(proc, idx, sel);

    // decoder 2 on selected tokens: sel -> y
    run_decoder(sel, KSEL, idx,
                ln1_2, cwq2, cwk2, cwv2, cwo2, ln2_2, cwg2, cwu2, cwd2,
                y, h, q, k, v, attn, x, ffg, ffu);

    // out[b, idx] = sel + sc*(y - sel)   (rest of d_out already = proc)
    scatter_k<<<B * KSEL, 256>>>(sel, y, sc, idx, (float*)d_out);
}

// round 16
// speedup vs baseline: 1.0987x; 1.0987x over previous
#include <cuda_runtime.h>
#include <math.h>
#include <stdint.h>

#define B 4
#define T 1024
#define D 1024
#define H 16
#define DH 64
#define FFN 4096
#define KSEL 256
#define EPSV 1e-6f
#define CVARF 1.0f
#define LOGCF 0.0f
#define BCE 1.0f
#define BCU 1.0f
#define NEGINF (-1.0e30f)
#define DD (D*D)

// ------------------------------- scratch (device globals; no allocation) ----
__device__ float g_h   [B*T*D];
__device__ float g_qkv [B*T*3*D];
__device__ float g_attn[B*T*D];
__device__ float g_x   [B*T*D];
__device__ float g_ffgu[B*T*2*FFN];
__device__ float g_ffg [B*T*FFN];
__device__ float g_mulv[B*T*2*D];
__device__ float g_dst [B*T];
__device__ float g_dch [B*T];
__device__ float g_gate[B*T];
__device__ float g_means[2];
__device__ int   g_idx [B*KSEL];
__device__ float g_sc  [B*KSEL];
__device__ float g_sel [B*KSEL*D];
__device__ float g_y   [B*KSEL*D];
// tf32-pre-rounded (concatenated) weights: 34 * DD floats total
__device__ float g_wbuf[(size_t)34*DD];

// ------------------------------- reductions --------------------------------
__device__ __forceinline__ float blockReduceSum(float v) {
    __shared__ float sh[32];
    int lane = threadIdx.x & 31, wid = threadIdx.x >> 5;
    #pragma unroll
    for (int o = 16; o > 0; o >>= 1) v += __shfl_xor_sync(0xffffffffu, v, o);
    if (lane == 0) sh[wid] = v;
    __syncthreads();
    int nw = (blockDim.x + 31) >> 5;
    float t = (threadIdx.x < nw) ? sh[threadIdx.x] : 0.f;
    if (wid == 0) {
        #pragma unroll
        for (int o = 16; o > 0; o >>= 1) t += __shfl_xor_sync(0xffffffffu, t, o);
        if (lane == 0) sh[0] = t;
    }
    __syncthreads();
    float r = sh[0];
    __syncthreads();
    return r;
}

// ------------------------------- tf32 helpers ------------------------------
__device__ __forceinline__ float f2tf32(float x) {
    uint32_t r;
    asm("cvt.rna.tf32.f32 %0, %1;" : "=r"(r) : "f"(x));
    return __uint_as_float(r);
}

__device__ __forceinline__ void mma_tf32(float c[4], const uint32_t a[4], const uint32_t b[2]) {
    asm volatile(
        "mma.sync.aligned.m16n8k8.row.col.f32.tf32.tf32.f32 "
        "{%0,%1,%2,%3}, {%4,%5,%6,%7}, {%8,%9}, {%0,%1,%2,%3};"
        : "+f"(c[0]), "+f"(c[1]), "+f"(c[2]), "+f"(c[3])
        : "r"(a[0]), "r"(a[1]), "r"(a[2]), "r"(a[3]), "r"(b[0]), "r"(b[1]));
}

__device__ __forceinline__ void cp16(uint32_t s, const float* g) {
    asm volatile("cp.async.cg.shared.global [%0], [%1], 16;" :: "r"(s), "l"(g));
}
__device__ __forceinline__ void cp_commit() { asm volatile("cp.async.commit_group;"); }
__device__ __forceinline__ void cp_wait0()  { asm volatile("cp.async.wait_group 0;"); }
__device__ __forceinline__ void cp_wait1()  { asm volatile("cp.async.wait_group 1;"); }

// ------------------------------- tf32 convert w/ column concat -------------
// in: [Rows][Cin] row-major -> out[r][colOff + c] with row width Cout.
__global__ void cvt_cat_k(const float* __restrict__ in, float* __restrict__ out,
                          int Cin4, int Cout4, int colOff4, int n4) {
    int i = blockIdx.x * blockDim.x + threadIdx.x;
    if (i >= n4) return;
    int r = i / Cin4, c = i % Cin4;
    float4 v = ((const float4*)in)[i];
    v.x = f2tf32(v.x); v.y = f2tf32(v.y); v.z = f2tf32(v.z); v.w = f2tf32(v.w);
    ((float4*)out)[(size_t)r * Cout4 + colOff4 + c] = v;
}

// ------------------------------- rmsnorm (output tf32-rounded) -------------
__global__ void rmsnorm_k(const float* __restrict__ x, const float* __restrict__ w,
                          float* __restrict__ o) {
    size_t row = blockIdx.x;
    const float4* xr = (const float4*)(x + row * D);
    float4 xv = xr[threadIdx.x];
    float ss = xv.x*xv.x + xv.y*xv.y + xv.z*xv.z + xv.w*xv.w;
    ss = blockReduceSum(ss);
    float rs = rsqrtf(ss / (float)D + EPSV);
    float4 wv = ((const float4*)w)[threadIdx.x];
    float4 ov = make_float4(f2tf32(xv.x*rs*wv.x), f2tf32(xv.y*rs*wv.y),
                            f2tf32(xv.z*rs*wv.z), f2tf32(xv.w*rs*wv.w));
    ((float4*)(o + row * D))[threadIdx.x] = ov;
}

// ------------------------------- GEMM tf32 (cp.async pipelined, BM=128) ----
__global__ __launch_bounds__(256, 2)
void gemm_tf32(const float* __restrict__ A, const float* __restrict__ Bm,
               const float* __restrict__ C0, float* __restrict__ C,
               int M, int N, int K)
{
    __shared__ float As[2][128][20];
    __shared__ float Bs[2][16][136];

    const int tid = threadIdx.x;
    const int warp = tid >> 5, lane = tid & 31;
    const int gid = lane >> 2, tig = lane & 3;
    const int wm = (warp & 1) * 64;
    const int wn = (warp >> 1) * 32;
    const int rowBase = blockIdx.y * 128;
    const int colBase = blockIdx.x * 128;

    const int aRow = tid >> 2;
    const int aCol = (tid & 3) << 2;
    const int bRow = tid >> 5;
    const int bCol = (tid & 31) << 2;

    const float* Ap = A + (size_t)(rowBase + aRow) * K + aCol;
    const float* Bp = Bm + (size_t)bRow * N + colBase + bCol;

    const uint32_t sA0 = (uint32_t)__cvta_generic_to_shared(&As[0][aRow][aCol]);
    const uint32_t sA1 = (uint32_t)__cvta_generic_to_shared(&As[0][aRow + 64][aCol]);
    const uint32_t sB0 = (uint32_t)__cvta_generic_to_shared(&Bs[0][bRow][bCol]);
    const uint32_t sB1 = (uint32_t)__cvta_generic_to_shared(&Bs[0][bRow + 8][bCol]);
    const uint32_t dAbuf = 128 * 20 * 4;
    const uint32_t dBbuf = 16 * 136 * 4;

    float acc[4][4][4];
    #pragma unroll
    for (int mt = 0; mt < 4; mt++)
        #pragma unroll
        for (int nt = 0; nt < 4; nt++)
            #pragma unroll
            for (int i = 0; i < 4; i++) acc[mt][nt][i] = 0.f;

    const int numT = K >> 4;

    cp16(sA0, Ap);
    cp16(sA1, Ap + (size_t)64 * K);
    cp16(sB0, Bp);
    cp16(sB1, Bp + (size_t)8 * N);
    cp_commit();

    for (int t = 0; t < numT; t++) {
        const int buf = t & 1;
        const bool hasNext = (t + 1 < numT);
        if (hasNext) {
            const int k0 = (t + 1) << 4;
            const uint32_t oA = (buf ^ 1) ? dAbuf : 0u;
            const uint32_t oB = (buf ^ 1) ? dBbuf : 0u;
            cp16(sA0 + oA, Ap + k0);
            cp16(sA1 + oA, Ap + (size_t)64 * K + k0);
            cp16(sB0 + oB, Bp + (size_t)k0 * N);
            cp16(sB1 + oB, Bp + (size_t)(k0 + 8) * N);
            cp_commit();
            cp_wait1();
        } else {
            cp_wait0();
        }
        __syncthreads();

        #pragma unroll
        for (int ks = 0; ks < 16; ks += 8) {
            const int kLo = ks + tig;
            const int kHi = kLo + 4;

            uint32_t af[4][4];
            #pragma unroll
            for (int mt = 0; mt < 4; mt++) {
                int m = wm + mt * 16 + gid;
                af[mt][0] = __float_as_uint(As[buf][m    ][kLo]);
                af[mt][1] = __float_as_uint(As[buf][m + 8][kLo]);
                af[mt][2] = __float_as_uint(As[buf][m    ][kHi]);
                af[mt][3] = __float_as_uint(As[buf][m + 8][kHi]);
            }
            uint32_t bf[4][2];
            #pragma unroll
            for (int nt = 0; nt < 4; nt++) {
                int n = wn + nt * 8 + gid;
                bf[nt][0] = __float_as_uint(Bs[buf][kLo][n]);
                bf[nt][1] = __float_as_uint(Bs[buf][kHi][n]);
            }
            #pragma unroll
            for (int mt = 0; mt < 4; mt++)
                #pragma unroll
                for (int nt = 0; nt < 4; nt++)
                    mma_tf32(acc[mt][nt], af[mt], bf[nt]);
        }
        __syncthreads();
    }

    #pragma unroll
    for (int mt = 0; mt < 4; mt++) {
        int r0 = rowBase + wm + mt * 16 + gid;
        int r1 = r0 + 8;
        #pragma unroll
        for (int nt = 0; nt < 4; nt++) {
            int c = colBase + wn + nt * 8 + tig * 2;
            size_t o0 = (size_t)r0 * N + c;
            size_t o1 = (size_t)r1 * N + c;
            float2 v0 = make_float2(acc[mt][nt][0], acc[mt][nt][1]);
            float2 v1 = make_float2(acc[mt][nt][2], acc[mt][nt][3]);
            if (C0) {
                float2 p0 = *(const float2*)(C0 + o0);
                float2 p1 = *(const float2*)(C0 + o1);
                v0.x += p0.x; v0.y += p0.y;
                v1.x += p1.x; v1.y += p1.y;
            }
            *(float2*)(C + o0) = v0;
            *(float2*)(C + o1) = v1;
        }
    }
}

// ------------------------------- GEMM tf32 small-M (BM=32) -----------------
__global__ __launch_bounds__(256)
void gemm_tf32_sm(const float* __restrict__ A, const float* __restrict__ Bm,
                  const float* __restrict__ C0, float* __restrict__ C,
                  int M, int N, int K)
{
    __shared__ float As[2][32][20];
    __shared__ float Bs[2][16][136];

    const int tid = threadIdx.x;
    const int warp = tid >> 5, lane = tid & 31;
    const int gid = lane >> 2, tig = lane & 3;
    const int wm = (warp & 1) * 16;
    const int wn = (warp >> 1) * 32;
    const int rowBase = blockIdx.y * 32;
    const int colBase = blockIdx.x * 128;

    const int aRow = tid >> 2;
    const int aCol = (tid & 3) << 2;
    const int bRow = tid >> 5;
    const int bCol = (tid & 31) << 2;
    const bool aAct = tid < 128;

    const float* Ap = A + (size_t)(rowBase + aRow) * K + aCol;
    const float* Bp = Bm + (size_t)bRow * N + colBase + bCol;

    const uint32_t sA0 = aAct ? (uint32_t)__cvta_generic_to_shared(&As[0][aRow][aCol]) : 0u;
    const uint32_t sB0 = (uint32_t)__cvta_generic_to_shared(&Bs[0][bRow][bCol]);
    const uint32_t sB1 = (uint32_t)__cvta_generic_to_shared(&Bs[0][bRow + 8][bCol]);
    const uint32_t dAbuf = 32 * 20 * 4;
    const uint32_t dBbuf = 16 * 136 * 4;

    float acc[4][4];
    #pragma unroll
    for (int nt = 0; nt < 4; nt++)
        #pragma unroll
        for (int i = 0; i < 4; i++) acc[nt][i] = 0.f;

    const int numT = K >> 4;

    if (aAct) cp16(sA0, Ap);
    cp16(sB0, Bp);
    cp16(sB1, Bp + (size_t)8 * N);
    cp_commit();

    for (int t = 0; t < numT; t++) {
        const int buf = t & 1;
        const bool hasNext = (t + 1 < numT);
        if (hasNext) {
            const int k0 = (t + 1) << 4;
            const uint32_t oA = (buf ^ 1) ? dAbuf : 0u;
            const uint32_t oB = (buf ^ 1) ? dBbuf : 0u;
            if (aAct) cp16(sA0 + oA, Ap + k0);
            cp16(sB0 + oB, Bp + (size_t)k0 * N);
            cp16(sB1 + oB, Bp + (size_t)(k0 + 8) * N);
            cp_commit();
            cp_wait1();
        } else {
            cp_wait0();
        }
        __syncthreads();

        #pragma unroll
        for (int ks = 0; ks < 16; ks += 8) {
            const int kLo = ks + tig;
            const int kHi = kLo + 4;
            uint32_t af[4];
            {
                int m = wm + gid;
                af[0] = __float_as_uint(As[buf][m    ][kLo]);
                af[1] = __float_as_uint(As[buf][m + 8][kLo]);
                af[2] = __float_as_uint(As[buf][m    ][kHi]);
                af[3] = __float_as_uint(As[buf][m + 8][kHi]);
            }
            #pragma unroll
            for (int nt = 0; nt < 4; nt++) {
                int n = wn + nt * 8 + gid;
                uint32_t bf[2];
                bf[0] = __float_as_uint(Bs[buf][kLo][n]);
                bf[1] = __float_as_uint(Bs[buf][kHi][n]);
                mma_tf32(acc[nt], af, bf);
            }
        }
        __syncthreads();
    }

    int r0 = rowBase + wm + gid;
    int r1 = r0 + 8;
    #pragma unroll
    for (int nt = 0; nt < 4; nt++) {
        int c = colBase + wn + nt * 8 + tig * 2;
        size_t o0 = (size_t)r0 * N + c;
        size_t o1 = (size_t)r1 * N + c;
        float2 v0 = make_float2(acc[nt][0], acc[nt][1]);
        float2 v1 = make_float2(acc[nt][2], acc[nt][3]);
        if (C0) {
            float2 p0 = *(const float2*)(C0 + o0);
            float2 p1 = *(const float2*)(C0 + o1);
            v0.x += p0.x; v0.y += p0.y;
            v1.x += p1.x; v1.y += p1.y;
        }
        *(float2*)(C + o0) = v0;
        *(float2*)(C + o1) = v1;
    }
}

static inline void launch_gemm(const float* A, const float* Bm, const float* C0,
                               float* C, int M, int N, int K)
{
    if (M <= 1024)
        gemm_tf32_sm<<<dim3(N / 128, M / 32), 256>>>(A, Bm, C0, C, M, N, K);
    else
        gemm_tf32<<<dim3(N / 128, M / 128), 256>>>(A, Bm, C0, C, M, N, K);
}

// ------------------------------- RoPE (in place, strided) ------------------
// x rows at stride ld; head h at +h*DH within row.
__global__ void rope_k(float* __restrict__ x, const int* __restrict__ posIdx,
                       int S, int ld) {
    int gid = blockIdx.x * blockDim.x + threadIdx.x;
    int total = B * S * H * (DH/2);
    if (gid >= total) return;
    int j = gid & 31;
    int h = (gid >> 5) & (H - 1);
    int sb = gid >> 9;
    int s = sb % S;
    int b = sb / S;
    float p = posIdx ? (float)posIdx[b * S + s] : (float)s;
    float inv = powf(10000.f, -(float)j / 32.f);
    float ang = p * inv;
    float c = cosf(ang), sn = sinf(ang);
    size_t base = (size_t)(b * S + s) * ld + h * DH;
    float x1 = x[base + j], x2 = x[base + 32 + j];
    x[base + j]      = x1 * c - x2 * sn;
    x[base + 32 + j] = x2 * c + x1 * sn;
}

// ------------------------------- fused flash attention ---------------------
// q,k,v rows at stride ldq (fused QKV buffer); output attn compact [M][H*DH].
#define FST 68
__global__ __launch_bounds__(256)
void flash_attn(const float* __restrict__ q, const float* __restrict__ k,
                const float* __restrict__ v, const float* __restrict__ o,
                int S, int ldq)
{
    extern __shared__ float sm[];
    float (*Qs)[FST] = (float(*)[FST])sm;
    float (*Ks)[FST] = (float(*)[FST])(sm + 64*FST);      // reused as Ps
    float (*Vt)[FST] = (float(*)[FST])(sm + 2*64*FST);    // [dh][token]
    __shared__ float redmx[2][64];
    __shared__ float redsm[2][64];

    const int bh = blockIdx.y;
    const int b = bh / H, h = bh % H;
    const int q0 = blockIdx.x * 64;
    const int tid = threadIdx.x, warp = tid >> 5, lane = tid & 31;
    const int gid = lane >> 2, tig = lane & 3;
    const int wm = (warp & 3) * 16;
    const int wn = (warp >> 2) * 32;
    const int warp_n = warp >> 2;

    #pragma unroll
    for (int i = 0; i < 4; i++) {
        int f4 = tid + i * 256;
        int r = f4 >> 4, c = (f4 & 15) << 2;
        float4 qv = *(const float4*)(q + (size_t)(b*S + q0 + r) * ldq + h*DH + c);
        Qs[r][c+0] = f2tf32(qv.x); Qs[r][c+1] = f2tf32(qv.y);
        Qs[r][c+2] = f2tf32(qv.z); Qs[r][c+3] = f2tf32(qv.w);
    }

    float mI[2] = {NEGINF, NEGINF};
    float lI[2] = {0.f, 0.f};
    float oacc[4][4];
    #pragma unroll
    for (int nt = 0; nt < 4; nt++)
        #pragma unroll
        for (int r = 0; r < 4; r++) oacc[nt][r] = 0.f;

    const int numKT = blockIdx.x + 1;
    for (int kt = 0; kt < numKT; kt++) {
        const int k0 = kt * 64;
        __syncthreads();
        #pragma unroll
        for (int i = 0; i < 4; i++) {
            int f4 = tid + i * 256;
            int r = f4 >> 4, c = (f4 & 15) << 2;
            size_t gbase = (size_t)(b*S + k0 + r) * ldq + h*DH + c;
            float4 kv = *(const float4*)(k + gbase);
            Ks[r][c+0] = f2tf32(kv.x); Ks[r][c+1] = f2tf32(kv.y);
            Ks[r][c+2] = f2tf32(kv.z); Ks[r][c+3] = f2tf32(kv.w);
            float4 vv = *(const float4*)(v + gbase);
            Vt[c+0][r] = f2tf32(vv.x); Vt[c+1][r] = f2tf32(vv.y);
            Vt[c+2][r] = f2tf32(vv.z); Vt[c+3][r] = f2tf32(vv.w);
        }
        __syncthreads();

        float sacc[4][4];
        #pragma unroll
        for (int nt = 0; nt < 4; nt++)
            #pragma unroll
            for (int r = 0; r < 4; r++) sacc[nt][r] = 0.f;

        #pragma unroll
        for (int ks = 0; ks < 64; ks += 8) {
            const int kLo = ks + tig, kHi = kLo + 4;
            uint32_t af[4];
            af[0] = __float_as_uint(Qs[wm + gid    ][kLo]);
            af[1] = __float_as_uint(Qs[wm + gid + 8][kLo]);
            af[2] = __float_as_uint(Qs[wm + gid    ][kHi]);
            af[3] = __float_as_uint(Qs[wm + gid + 8][kHi]);
            #pragma unroll
            for (int nt = 0; nt < 4; nt++) {
                uint32_t bf[2];
                bf[0] = __float_as_uint(Ks[wn + nt*8 + gid][kLo]);
                bf[1] = __float_as_uint(Ks[wn + nt*8 + gid][kHi]);
                mma_tf32(sacc[nt], af, bf);
            }
        }

        const float scale = 0.125f;
        const bool diag = (kt == numKT - 1);
        #pragma unroll
        for (int nt = 0; nt < 4; nt++)
            #pragma unroll
            for (int r = 0; r < 4; r++) {
                int rowg = q0 + wm + gid + ((r >> 1) << 3);
                int colg = k0 + wn + nt*8 + tig*2 + (r & 1);
                float sv = sacc[nt][r] * scale;
                sacc[nt][r] = (diag && colg > rowg) ? NEGINF : sv;
            }

        float rmx[2];
        #pragma unroll
        for (int j = 0; j < 2; j++) {
            float m0 = fmaxf(sacc[0][2*j], sacc[0][2*j+1]);
            #pragma unroll
            for (int nt = 1; nt < 4; nt++)
                m0 = fmaxf(m0, fmaxf(sacc[nt][2*j], sacc[nt][2*j+1]));
            m0 = fmaxf(m0, __shfl_xor_sync(0xffffffffu, m0, 1));
            m0 = fmaxf(m0, __shfl_xor_sync(0xffffffffu, m0, 2));
            rmx[j] = m0;
        }
        if (tig == 0) {
            redmx[warp_n][wm + gid    ] = rmx[0];
            redmx[warp_n][wm + gid + 8] = rmx[1];
        }
        __syncthreads();
        rmx[0] = fmaxf(redmx[0][wm + gid    ], redmx[1][wm + gid    ]);
        rmx[1] = fmaxf(redmx[0][wm + gid + 8], redmx[1][wm + gid + 8]);

        float mnew[2], alpha[2];
        #pragma unroll
        for (int j = 0; j < 2; j++) {
            mnew[j] = fmaxf(mI[j], rmx[j]);
            alpha[j] = expf(mI[j] - mnew[j]);
            mI[j] = mnew[j];
        }

        float rsum[2] = {0.f, 0.f};
        #pragma unroll
        for (int nt = 0; nt < 4; nt++)
            #pragma unroll
            for (int r = 0; r < 4; r++) {
                int j = r >> 1;
                float p = expf(sacc[nt][r] - mnew[j]);
                rsum[j] += p;
                Ks[wm + gid + (j << 3)][wn + nt*8 + tig*2 + (r & 1)] = f2tf32(p);
            }
        #pragma unroll
        for (int j = 0; j < 2; j++) {
            rsum[j] += __shfl_xor_sync(0xffffffffu, rsum[j], 1);
            rsum[j] += __shfl_xor_sync(0xffffffffu, rsum[j], 2);
        }
        if (tig == 0) {
            redsm[warp_n][wm + gid    ] = rsum[0];
            redsm[warp_n][wm + gid + 8] = rsum[1];
        }
        __syncthreads();
        rsum[0] = redsm[0][wm + gid    ] + redsm[1][wm + gid    ];
        rsum[1] = redsm[0][wm + gid + 8] + redsm[1][wm + gid + 8];

        #pragma unroll
        for (int j = 0; j < 2; j++) lI[j] = alpha[j] * lI[j] + rsum[j];
        #pragma unroll
        for (int nt = 0; nt < 4; nt++) {
            oacc[nt][0] *= alpha[0]; oacc[nt][1] *= alpha[0];
            oacc[nt][2] *= alpha[1]; oacc[nt][3] *= alpha[1];
        }

        #pragma unroll
        for (int ks = 0; ks < 64; ks += 8) {
            const int kLo = ks + tig, kHi = kLo + 4;
            uint32_t af[4];
            af[0] = __float_as_uint(Ks[wm + gid    ][kLo]);
            af[1] = __float_as_uint(Ks[wm + gid + 8][kLo]);
            af[2] = __float_as_uint(Ks[wm + gid    ][kHi]);
            af[3] = __float_as_uint(Ks[wm + gid + 8][kHi]);
            #pragma unroll
            for (int nt = 0; nt < 4; nt++) {
                uint32_t bf[2];
                bf[0] = __float_as_uint(Vt[wn + nt*8 + gid][kLo]);
                bf[1] = __float_as_uint(Vt[wn + nt*8 + gid][kHi]);
                mma_tf32(oacc[nt], af, bf);
            }
        }
    }

    float inv0 = 1.f / lI[0], inv1 = 1.f / lI[1];
    float* op = (float*)o;
    #pragma unroll
    for (int nt = 0; nt < 4; nt++) {
        int col = h*DH + wn + nt*8 + tig*2;
        size_t r0 = ((size_t)(b*S + q0 + wm + gid)) * (H*DH) + col;
        size_t r1 = ((size_t)(b*S + q0 + wm + gid + 8)) * (H*DH) + col;
        *(float2*)(op + r0) = make_float2(f2tf32(oacc[nt][0]*inv0), f2tf32(oacc[nt][1]*inv0));
        *(float2*)(op + r1) = make_float2(f2tf32(oacc[nt][2]*inv1), f2tf32(oacc[nt][3]*inv1));
    }
}

// ------------------------------- SwiGLU from fused GU buffer ---------------
// gu: [M][2*FFN]; out: [M][FFN] (tf32-rounded)
__global__ void silu_mul_gu(const float* __restrict__ gu, float* __restrict__ out, int n4) {
    int i = blockIdx.x * blockDim.x + threadIdx.x;
    if (i >= n4) return;
    const int cW = FFN / 4;
    int r = i / cW, c = i % cW;
    float4 gv = ((const float4*)gu)[(size_t)r * (2 * cW) + c];
    float4 uv = ((const float4*)gu)[(size_t)r * (2 * cW) + cW + c];
    gv.x = f2tf32(gv.x / (1.f + expf(-gv.x)) * uv.x);
    gv.y = f2tf32(gv.y / (1.f + expf(-gv.y)) * uv.y);
    gv.z = f2tf32(gv.z / (1.f + expf(-gv.z)) * uv.z);
    gv.w = f2tf32(gv.w / (1.f + expf(-gv.w)) * uv.w);
    ((float4*)out)[i] = gv;
}

// ------------------------------- router ------------------------------------
__global__ void router_stats(const float* __restrict__ proc, const float* __restrict__ hid,
                             const float* __restrict__ mulv,
                             float* __restrict__ dst, float* __restrict__ dch)
{
    size_t row = blockIdx.x;
    const float* pr = proc + row * D;
    const float* hi = hid + row * D;
    const float* mu = mulv + row * (2 * D);
    const float* lv = mu + D;
    float s1 = 0.f, s2 = 0.f;
    for (int i = threadIdx.x; i < D; i += 256) {
        float r = pr[i] - hi[i];
        s1 += r * r;
        float l = lv[i];
        float dm = r - mu[i];
        s2 += 0.5f * (l - LOGCF + (CVARF + dm * dm) * expf(-l) - 1.0f);
    }
    s1 = blockReduceSum(s1);
    s2 = blockReduceSum(s2);
    if (threadIdx.x == 0) {
        dst[row] = s1 / (float)D;
        dch[row] = s2 / (float)D;
    }
}

__global__ void router_means(const float* __restrict__ dst, const float* __restrict__ dch,
                             float* __restrict__ means)
{
    float s1 = 0.f, s2 = 0.f;
    for (int i = threadIdx.x; i < B * T; i += 1024) { s1 += dst[i]; s2 += dch[i]; }
    s1 = blockReduceSum(s1);
    s2 = blockReduceSum(s2);
    if (threadIdx.x == 0) {
        means[0] = s1 / (float)(B * T);
        means[1] = s2 / (float)(B * T);
    }
}

__global__ void router_gate(const float* __restrict__ dst, const float* __restrict__ dch,
                            const float* __restrict__ means, float* __restrict__ g)
{
    int i = blockIdx.x * blockDim.x + threadIdx.x;
    if (i >= B * T) return;
    float z = BCE * (dst[i] - means[0]) + BCU * (dch[i] - means[1]);
    g[i] = 1.f / (1.f + expf(-z));
}

__global__ void topk_k(const float* __restrict__ g, int* __restrict__ idxO,
                       float* __restrict__ scO)
{
    int b = blockIdx.x;
    int i = threadIdx.x;
    __shared__ float gs[T];
    __shared__ unsigned char flag[T];
    gs[i] = g[b * T + i];
    __syncthreads();
    float gi = gs[i];
    int rank = 0;
    for (int j = 0; j < T; j++) {
        float gj = gs[j];
        rank += (gj > gi) || (gj == gi && j < i);
    }
    flag[i] = (rank < KSEL) ? 1 : 0;
    __syncthreads();
    if (flag[i]) {
        int pos = 0;
        for (int j = 0; j < i; j++) pos += flag[j];
        idxO[b * KSEL + pos] = i;
        scO[b * KSEL + pos] = gi;
    }
}

// ------------------------------- gather / scatter --------------------------
__global__ void gather_k(const float* __restrict__ proc, const int* __restrict__ idx,
                         float* __restrict__ sel)
{
    int row = blockIdx.x;
    int b = row / KSEL;
    int src = idx[row];
    const float4* s4 = (const float4*)(proc + ((size_t)b * T + src) * D);
    float4* d4 = (float4*)(sel + (size_t)row * D);
    d4[threadIdx.x] = s4[threadIdx.x];
}

__global__ void scatter_k(const float* __restrict__ sel, const float* __restrict__ y,
                          const float* __restrict__ sc, const int* __restrict__ idx,
                          float* __restrict__ out)
{
    int row = blockIdx.x;
    int b = row / KSEL;
    float s = sc[row];
    size_t drow = ((size_t)b * T + idx[row]) * D;
    const float4* s4 = (const float4*)(sel + (size_t)row * D);
    const float4* y4 = (const float4*)(y + (size_t)row * D);
    float4 sv = s4[threadIdx.x];
    float4 yv = y4[threadIdx.x];
    float4 ov = make_float4(sv.x + s * (yv.x - sv.x),
                            sv.y + s * (yv.y - sv.y),
                            sv.z + s * (yv.z - sv.z),
                            sv.w + s * (yv.w - sv.w));
    ((float4*)(out + drow))[threadIdx.x] = ov;
}

// ------------------------------- host: decoder pipeline --------------------
#define FLASH_SMEM (3 * 64 * FST * 4)

static void run_decoder(const float* x_in, int S, const int* posIdx,
                        const float* ln1, const float* wqkv, const float* wo,
                        const float* ln2, const float* wgu, const float* wd,
                        float* out,
                        float* h, float* qkv, float* attn,
                        float* x, float* ffgu, float* ffg)
{
    const int M = B * S;
    rmsnorm_k<<<M, 256>>>(x_in, ln1, h);
    launch_gemm(h, wqkv, nullptr, qkv, M, 3 * D, D);
    int ropeTotal = B * S * H * (DH / 2);
    rope_k<<<(ropeTotal + 255) / 256, 256>>>(qkv,     posIdx, S, 3 * D);  // q part
    rope_k<<<(ropeTotal + 255) / 256, 256>>>(qkv + D, posIdx, S, 3 * D);  // k part
    flash_attn<<<dim3(S / 64, B * H), 256, FLASH_SMEM>>>(qkv, qkv + D, qkv + 2 * D,
                                                         attn, S, 3 * D);
    launch_gemm(attn, wo, x_in, x, M, D, D);
    rmsnorm_k<<<M, 256>>>(x, ln2, h);
    launch_gemm(h, wgu, nullptr, ffgu, M, 2 * FFN, D);
    int n4 = M * FFN / 4;
    silu_mul_gu<<<(n4 + 255) / 256, 256>>>(ffgu, ffg, n4);
    launch_gemm(ffg, wd, x, out, M, D, FFN);
}

// ------------------------------- entry -------------------------------------
extern "C" void kernel_launch(void* const* d_in, const int* in_sizes, int n_in,
                              void* d_out, int out_size)
{
    if (n_in < 21) return;
    const float* in[21];
    for (int i = 0; i < 21; i++) in[i] = (const float*)d_in[i];

    const float *hidden, *ln1_1, *wq1, *wk1, *wv1, *wo1, *ln2_1, *wg1, *wu1, *wd1;
    const float *ln1_2, *wq2, *wk2, *wv2, *wo2, *ln2_2, *wg2, *wu2, *wd2, *pnw, *pw;

    if (in_sizes[1] == D) {
        hidden = in[0];  ln1_1 = in[1];  wq1 = in[2];  wk1 = in[3];  wv1 = in[4];
        wo1 = in[5];     ln2_1 = in[6];  wg1 = in[7];  wu1 = in[8];  wd1 = in[9];
        ln1_2 = in[10];  wq2 = in[11];   wk2 = in[12]; wv2 = in[13]; wo2 = in[14];
        ln2_2 = in[15];  wg2 = in[16];   wu2 = in[17]; wd2 = in[18];
        pnw = in[19];    pw = in[20];
    } else {
        hidden = in[0];
        wq1 = in[1];  wk1 = in[2];  wv1 = in[3];  wo1 = in[4];
        wq2 = in[5];  wk2 = in[6];  wv2 = in[7];  wo2 = in[8];
        wg1 = in[9];  wu1 = in[10]; wd1 = in[11];
        wg2 = in[12]; wu2 = in[13]; wd2 = in[14];
        ln1_1 = in[15]; ln2_1 = in[16]; ln1_2 = in[17]; ln2_2 = in[18];
        pnw = in[19]; pw = in[20];
    }

    cudaFuncSetAttribute(flash_attn, cudaFuncAttributeMaxDynamicSharedMemorySize,
                         FLASH_SMEM);

    float *h, *qkv, *attn, *x, *ffgu, *ffg, *mulv;
    float *dst, *dch, *gate, *means, *sc, *sel, *y, *wbuf;
    int* idx;
    cudaGetSymbolAddress((void**)&h, g_h);
    cudaGetSymbolAddress((void**)&qkv, g_qkv);
    cudaGetSymbolAddress((void**)&attn, g_attn);
    cudaGetSymbolAddress((void**)&x, g_x);
    cudaGetSymbolAddress((void**)&ffgu, g_ffgu);
    cudaGetSymbolAddress((void**)&ffg, g_ffg);
    cudaGetSymbolAddress((void**)&mulv, g_mulv);
    cudaGetSymbolAddress((void**)&dst, g_dst);
    cudaGetSymbolAddress((void**)&dch, g_dch);
    cudaGetSymbolAddress((void**)&gate, g_gate);
    cudaGetSymbolAddress((void**)&means, g_means);
    cudaGetSymbolAddress((void**)&idx, g_idx);
    cudaGetSymbolAddress((void**)&sc, g_sc);
    cudaGetSymbolAddress((void**)&sel, g_sel);
    cudaGetSymbolAddress((void**)&y, g_y);
    cudaGetSymbolAddress((void**)&wbuf, g_wbuf);

    // concatenated tf32 weight copies
    float* cwqkv1 = wbuf;                          // [D][3D]
    float* cwqkv2 = wbuf + (size_t)3 * DD;         // [D][3D]
    float* cwo1   = wbuf + (size_t)6 * DD;         // [D][D]
    float* cwo2   = wbuf + (size_t)7 * DD;         // [D][D]
    float* cpw    = wbuf + (size_t)8 * DD;         // [D][2D]
    float* cwgu1  = wbuf + (size_t)10 * DD;        // [D][2*FFN]
    float* cwgu2  = wbuf + (size_t)18 * DD;        // [D][2*FFN]
    float* cwd1   = wbuf + (size_t)26 * DD;        // [FFN][D]
    float* cwd2   = wbuf + (size_t)30 * DD;        // [FFN][D]

    const int nDD4 = DD / 4, nDF4 = D * FFN / 4, nP4 = 2 * DD / 4;
    const int D4 = D / 4, F4 = FFN / 4;
    // QKV concat: rows=D, Cin=D, Cout=3D
    cvt_cat_k<<<(nDD4 + 255) / 256, 256>>>(wq1, cwqkv1, D4, 3 * D4, 0,      nDD4);
    cvt_cat_k<<<(nDD4 + 255) / 256, 256>>>(wk1, cwqkv1, D4, 3 * D4, D4,     nDD4);
    cvt_cat_k<<<(nDD4 + 255) / 256, 256>>>(wv1, cwqkv1, D4, 3 * D4, 2 * D4, nDD4);
    cvt_cat_k<<<(nDD4 + 255) / 256, 256>>>(wq2, cwqkv2, D4, 3 * D4, 0,      nDD4);
    cvt_cat_k<<<(nDD4 + 255) / 256, 256>>>(wk2, cwqkv2, D4, 3 * D4, D4,     nDD4);
    cvt_cat_k<<<(nDD4 + 255) / 256, 256>>>(wv2, cwqkv2, D4, 3 * D4, 2 * D4, nDD4);
    // plain copies
    cvt_cat_k<<<(nDD4 + 255) / 256, 256>>>(wo1, cwo1, D4, D4, 0, nDD4);
    cvt_cat_k<<<(nDD4 + 255) / 256, 256>>>(wo2, cwo2, D4, D4, 0, nDD4);
    cvt_cat_k<<<(nP4 + 255) / 256, 256>>>(pw, cpw, 2 * D4, 2 * D4, 0, nP4);
    // GU concat: rows=D, Cin=FFN, Cout=2*FFN
    cvt_cat_k<<<(nDF4 + 255) / 256, 256>>>(wg1, cwgu1, F4, 2 * F4, 0,  nDF4);
    cvt_cat_k<<<(nDF4 + 255) / 256, 256>>>(wu1, cwgu1, F4, 2 * F4, F4, nDF4);
    cvt_cat_k<<<(nDF4 + 255) / 256, 256>>>(wg2, cwgu2, F4, 2 * F4, 0,  nDF4);
    cvt_cat_k<<<(nDF4 + 255) / 256, 256>>>(wu2, cwgu2, F4, 2 * F4, F4, nDF4);
    // wd plain: rows=FFN, Cin=D
    cvt_cat_k<<<(nDF4 + 255) / 256, 256>>>(wd1, cwd1, D4, D4, 0, nDF4);
    cvt_cat_k<<<(nDF4 + 255) / 256, 256>>>(wd2, cwd2, D4, D4, 0, nDF4);

    float* proc = (float*)d_out;   // decoder1 writes the output buffer directly

    // decoder 1: hidden -> proc (= d_out)
    run_decoder(hidden, T, nullptr,
                ln1_1, cwqkv1, cwo1, ln2_1, cwgu1, cwd1,
                proc, h, qkv, attn, x, ffgu, ffg);

    // router
    rmsnorm_k<<<B * T, 256>>>(hidden, pnw, h);
    launch_gemm(h, cpw, nullptr, mulv, B * T, 2 * D, D);
    router_stats<<<B * T, 256>>>(proc, hidden, mulv, dst, dch);
    router_means<<<1, 1024>>>(dst, dch, means);
    router_gate<<<(B * T + 255) / 256, 256>>>(dst, dch, means, gate);
    topk_k<<<B, 1024>>>(gate, idx, sc);
    gather_k<<<B * KSEL, 256>>>(proc, idx, sel);

    // decoder 2 on selected tokens: sel -> y
    run_decoder(sel, KSEL, idx,
                ln1_2, cwqkv2, cwo2, ln2_2, cwgu2, cwd2,
                y, h, qkv, attn, x, ffgu, ffg);

    // out[b, idx] = sel + sc*(y - sel)   (rest of d_out already = proc)
    scatter_k<<<B * KSEL, 256>>>(sel, y, sc, idx, (float*)d_out);
}

// round 17
// speedup vs baseline: 1.1461x; 1.0431x over previous
#include <cuda_runtime.h>
#include <math.h>
#include <stdint.h>

#define B 4
#define T 1024
#define D 1024
#define H 16
#define DH 64
#define FFN 4096
#define KSEL 256
#define EPSV 1e-6f
#define CVARF 1.0f
#define LOGCF 0.0f
#define BCE 1.0f
#define BCU 1.0f
#define NEGINF (-1.0e30f)

// ------------------------------- scratch (device globals; no allocation) ----
__device__ float g_h   [B*T*D];
__device__ float g_qkv [B*T*3*D];
__device__ float g_attn[B*T*D];
__device__ float g_x   [B*T*D];
__device__ float g_ffgu[B*T*2*FFN];
__device__ float g_ffg [B*T*FFN];
__device__ float g_mulv[B*T*2*D];
__device__ float g_dst [B*T];
__device__ float g_dch [B*T];
__device__ float g_gate[B*T];
__device__ float g_means[2];
__device__ int   g_idx [B*KSEL];
__device__ float g_sc  [B*KSEL];
__device__ float g_sel [B*KSEL*D];
__device__ float g_y   [B*KSEL*D];

// ------------------------------- reductions --------------------------------
__device__ __forceinline__ float blockReduceSum(float v) {
    __shared__ float sh[32];
    int lane = threadIdx.x & 31, wid = threadIdx.x >> 5;
    #pragma unroll
    for (int o = 16; o > 0; o >>= 1) v += __shfl_xor_sync(0xffffffffu, v, o);
    if (lane == 0) sh[wid] = v;
    __syncthreads();
    int nw = (blockDim.x + 31) >> 5;
    float t = (threadIdx.x < nw) ? sh[threadIdx.x] : 0.f;
    if (wid == 0) {
        #pragma unroll
        for (int o = 16; o > 0; o >>= 1) t += __shfl_xor_sync(0xffffffffu, t, o);
        if (lane == 0) sh[0] = t;
    }
    __syncthreads();
    float r = sh[0];
    __syncthreads();
    return r;
}

// ------------------------------- tf32 helpers ------------------------------
__device__ __forceinline__ float f2tf32(float x) {
    uint32_t r;
    asm("cvt.rna.tf32.f32 %0, %1;" : "=r"(r) : "f"(x));
    return __uint_as_float(r);
}

__device__ __forceinline__ void mma_tf32(float c[4], const uint32_t a[4], const uint32_t b[2]) {
    asm volatile(
        "mma.sync.aligned.m16n8k8.row.col.f32.tf32.tf32.f32 "
        "{%0,%1,%2,%3}, {%4,%5,%6,%7}, {%8,%9}, {%0,%1,%2,%3};"
        : "+f"(c[0]), "+f"(c[1]), "+f"(c[2]), "+f"(c[3])
        : "r"(a[0]), "r"(a[1]), "r"(a[2]), "r"(a[3]), "r"(b[0]), "r"(b[1]));
}

__device__ __forceinline__ void cp16(uint32_t s, const float* g) {
    asm volatile("cp.async.cg.shared.global [%0], [%1], 16;" :: "r"(s), "l"(g));
}
__device__ __forceinline__ void cp_commit() { asm volatile("cp.async.commit_group;"); }
__device__ __forceinline__ void cp_wait0()  { asm volatile("cp.async.wait_group 0;"); }
__device__ __forceinline__ void cp_wait1()  { asm volatile("cp.async.wait_group 1;"); }

// ------------------------------- rmsnorm (output tf32-rounded) -------------
__global__ void rmsnorm_k(const float* __restrict__ x, const float* __restrict__ w,
                          float* __restrict__ o) {
    size_t row = blockIdx.x;
    const float4* xr = (const float4*)(x + row * D);
    float4 xv = xr[threadIdx.x];
    float ss = xv.x*xv.x + xv.y*xv.y + xv.z*xv.z + xv.w*xv.w;
    ss = blockReduceSum(ss);
    float rs = rsqrtf(ss / (float)D + EPSV);
    float4 wv = ((const float4*)w)[threadIdx.x];
    float4 ov = make_float4(f2tf32(xv.x*rs*wv.x), f2tf32(xv.y*rs*wv.y),
                            f2tf32(xv.z*rs*wv.z), f2tf32(xv.w*rs*wv.w));
    ((float4*)(o + row * D))[threadIdx.x] = ov;
}

// ------------------------------- GEMM tf32, segmented B (BM=128) -----------
// C[M,N] = A[M,K] @ concat(B0,B1,B2)[K,N] (+ C0).  Each Bseg is [K][Nseg]
// row-major with row stride Nseg; segment chosen per CTA from colBase.
// TF32 tensor cores round FP32 operands internally (cuBLAS TF32 semantics),
// so raw weights are fed directly; A is tf32-rounded by its producers.
__global__ __launch_bounds__(256, 2)
void gemm_tf32(const float* __restrict__ A,
               const float* __restrict__ B0, const float* __restrict__ B1,
               const float* __restrict__ B2,
               const float* __restrict__ C0, float* __restrict__ C,
               int M, int N, int K, int Nseg)
{
    __shared__ float As[2][128][20];
    __shared__ float Bs[2][16][136];

    const int tid = threadIdx.x;
    const int warp = tid >> 5, lane = tid & 31;
    const int gid = lane >> 2, tig = lane & 3;
    const int wm = (warp & 1) * 64;
    const int wn = (warp >> 1) * 32;
    const int rowBase = blockIdx.y * 128;
    const int colBase = blockIdx.x * 128;

    const int seg = colBase / Nseg;
    const float* Bm = (seg == 0) ? B0 : ((seg == 1) ? B1 : B2);
    const int colInSeg = colBase - seg * Nseg;

    const int aRow = tid >> 2;
    const int aCol = (tid & 3) << 2;
    const int bRow = tid >> 5;
    const int bCol = (tid & 31) << 2;

    const float* Ap = A + (size_t)(rowBase + aRow) * K + aCol;
    const float* Bp = Bm + (size_t)bRow * Nseg + colInSeg + bCol;

    const uint32_t sA0 = (uint32_t)__cvta_generic_to_shared(&As[0][aRow][aCol]);
    const uint32_t sA1 = (uint32_t)__cvta_generic_to_shared(&As[0][aRow + 64][aCol]);
    const uint32_t sB0 = (uint32_t)__cvta_generic_to_shared(&Bs[0][bRow][bCol]);
    const uint32_t sB1 = (uint32_t)__cvta_generic_to_shared(&Bs[0][bRow + 8][bCol]);
    const uint32_t dAbuf = 128 * 20 * 4;
    const uint32_t dBbuf = 16 * 136 * 4;

    float acc[4][4][4];
    #pragma unroll
    for (int mt = 0; mt < 4; mt++)
        #pragma unroll
        for (int nt = 0; nt < 4; nt++)
            #pragma unroll
            for (int i = 0; i < 4; i++) acc[mt][nt][i] = 0.f;

    const int numT = K >> 4;

    cp16(sA0, Ap);
    cp16(sA1, Ap + (size_t)64 * K);
    cp16(sB0, Bp);
    cp16(sB1, Bp + (size_t)8 * Nseg);
    cp_commit();

    for (int t = 0; t < numT; t++) {
        const int buf = t & 1;
        const bool hasNext = (t + 1 < numT);
        if (hasNext) {
            const int k0 = (t + 1) << 4;
            const uint32_t oA = (buf ^ 1) ? dAbuf : 0u;
            const uint32_t oB = (buf ^ 1) ? dBbuf : 0u;
            cp16(sA0 + oA, Ap + k0);
            cp16(sA1 + oA, Ap + (size_t)64 * K + k0);
            cp16(sB0 + oB, Bp + (size_t)k0 * Nseg);
            cp16(sB1 + oB, Bp + (size_t)(k0 + 8) * Nseg);
            cp_commit();
            cp_wait1();
        } else {
            cp_wait0();
        }
        __syncthreads();

        #pragma unroll
        for (int ks = 0; ks < 16; ks += 8) {
            const int kLo = ks + tig;
            const int kHi = kLo + 4;

            uint32_t af[4][4];
            #pragma unroll
            for (int mt = 0; mt < 4; mt++) {
                int m = wm + mt * 16 + gid;
                af[mt][0] = __float_as_uint(As[buf][m    ][kLo]);
                af[mt][1] = __float_as_uint(As[buf][m + 8][kLo]);
                af[mt][2] = __float_as_uint(As[buf][m    ][kHi]);
                af[mt][3] = __float_as_uint(As[buf][m + 8][kHi]);
            }
            uint32_t bf[4][2];
            #pragma unroll
            for (int nt = 0; nt < 4; nt++) {
                int n = wn + nt * 8 + gid;
                bf[nt][0] = __float_as_uint(Bs[buf][kLo][n]);
                bf[nt][1] = __float_as_uint(Bs[buf][kHi][n]);
            }
            #pragma unroll
            for (int mt = 0; mt < 4; mt++)
                #pragma unroll
                for (int nt = 0; nt < 4; nt++)
                    mma_tf32(acc[mt][nt], af[mt], bf[nt]);
        }
        __syncthreads();
    }

    #pragma unroll
    for (int mt = 0; mt < 4; mt++) {
        int r0 = rowBase + wm + mt * 16 + gid;
        int r1 = r0 + 8;
        #pragma unroll
        for (int nt = 0; nt < 4; nt++) {
            int c = colBase + wn + nt * 8 + tig * 2;
            size_t o0 = (size_t)r0 * N + c;
            size_t o1 = (size_t)r1 * N + c;
            float2 v0 = make_float2(acc[mt][nt][0], acc[mt][nt][1]);
            float2 v1 = make_float2(acc[mt][nt][2], acc[mt][nt][3]);
            if (C0) {
                float2 p0 = *(const float2*)(C0 + o0);
                float2 p1 = *(const float2*)(C0 + o1);
                v0.x += p0.x; v0.y += p0.y;
                v1.x += p1.x; v1.y += p1.y;
            }
            *(float2*)(C + o0) = v0;
            *(float2*)(C + o1) = v1;
        }
    }
}

// ------------------------------- GEMM tf32 small-M, segmented B (BM=32) ----
__global__ __launch_bounds__(256)
void gemm_tf32_sm(const float* __restrict__ A,
                  const float* __restrict__ B0, const float* __restrict__ B1,
                  const float* __restrict__ B2,
                  const float* __restrict__ C0, float* __restrict__ C,
                  int M, int N, int K, int Nseg)
{
    __shared__ float As[2][32][20];
    __shared__ float Bs[2][16][136];

    const int tid = threadIdx.x;
    const int warp = tid >> 5, lane = tid & 31;
    const int gid = lane >> 2, tig = lane & 3;
    const int wm = (warp & 1) * 16;
    const int wn = (warp >> 1) * 32;
    const int rowBase = blockIdx.y * 32;
    const int colBase = blockIdx.x * 128;

    const int seg = colBase / Nseg;
    const float* Bm = (seg == 0) ? B0 : ((seg == 1) ? B1 : B2);
    const int colInSeg = colBase - seg * Nseg;

    const int aRow = tid >> 2;
    const int aCol = (tid & 3) << 2;
    const int bRow = tid >> 5;
    const int bCol = (tid & 31) << 2;
    const bool aAct = tid < 128;

    const float* Ap = A + (size_t)(rowBase + aRow) * K + aCol;
    const float* Bp = Bm + (size_t)bRow * Nseg + colInSeg + bCol;

    const uint32_t sA0 = aAct ? (uint32_t)__cvta_generic_to_shared(&As[0][aRow][aCol]) : 0u;
    const uint32_t sB0 = (uint32_t)__cvta_generic_to_shared(&Bs[0][bRow][bCol]);
    const uint32_t sB1 = (uint32_t)__cvta_generic_to_shared(&Bs[0][bRow + 8][bCol]);
    const uint32_t dAbuf = 32 * 20 * 4;
    const uint32_t dBbuf = 16 * 136 * 4;

    float acc[4][4];
    #pragma unroll
    for (int nt = 0; nt < 4; nt++)
        #pragma unroll
        for (int i = 0; i < 4; i++) acc[nt][i] = 0.f;

    const int numT = K >> 4;

    if (aAct) cp16(sA0, Ap);
    cp16(sB0, Bp);
    cp16(sB1, Bp + (size_t)8 * Nseg);
    cp_commit();

    for (int t = 0; t < numT; t++) {
        const int buf = t & 1;
        const bool hasNext = (t + 1 < numT);
        if (hasNext) {
            const int k0 = (t + 1) << 4;
            const uint32_t oA = (buf ^ 1) ? dAbuf : 0u;
            const uint32_t oB = (buf ^ 1) ? dBbuf : 0u;
            if (aAct) cp16(sA0 + oA, Ap + k0);
            cp16(sB0 + oB, Bp + (size_t)k0 * Nseg);
            cp16(sB1 + oB, Bp + (size_t)(k0 + 8) * Nseg);
            cp_commit();
            cp_wait1();
        } else {
            cp_wait0();
        }
        __syncthreads();

        #pragma unroll
        for (int ks = 0; ks < 16; ks += 8) {
            const int kLo = ks + tig;
            const int kHi = kLo + 4;
            uint32_t af[4];
            {
                int m = wm + gid;
                af[0] = __float_as_uint(As[buf][m    ][kLo]);
                af[1] = __float_as_uint(As[buf][m + 8][kLo]);
                af[2] = __float_as_uint(As[buf][m    ][kHi]);
                af[3] = __float_as_uint(As[buf][m + 8][kHi]);
            }
            #pragma unroll
            for (int nt = 0; nt < 4; nt++) {
                int n = wn + nt * 8 + gid;
                uint32_t bf[2];
                bf[0] = __float_as_uint(Bs[buf][kLo][n]);
                bf[1] = __float_as_uint(Bs[buf][kHi][n]);
                mma_tf32(acc[nt], af, bf);
            }
        }
        __syncthreads();
    }

    int r0 = rowBase + wm + gid;
    int r1 = r0 + 8;
    #pragma unroll
    for (int nt = 0; nt < 4; nt++) {
        int c = colBase + wn + nt * 8 + tig * 2;
        size_t o0 = (size_t)r0 * N + c;
        size_t o1 = (size_t)r1 * N + c;
        float2 v0 = make_float2(acc[nt][0], acc[nt][1]);
        float2 v1 = make_float2(acc[nt][2], acc[nt][3]);
        if (C0) {
            float2 p0 = *(const float2*)(C0 + o0);
            float2 p1 = *(const float2*)(C0 + o1);
            v0.x += p0.x; v0.y += p0.y;
            v1.x += p1.x; v1.y += p1.y;
        }
        *(float2*)(C + o0) = v0;
        *(float2*)(C + o1) = v1;
    }
}

static inline void launch_gemm3(const float* A, const float* B0, const float* B1,
                                const float* B2, const float* C0, float* C,
                                int M, int N, int K, int Nseg)
{
    if (M <= 1024)
        gemm_tf32_sm<<<dim3(N / 128, M / 32), 256>>>(A, B0, B1, B2, C0, C, M, N, K, Nseg);
    else
        gemm_tf32<<<dim3(N / 128, M / 128), 256>>>(A, B0, B1, B2, C0, C, M, N, K, Nseg);
}

// ------------------------------- RoPE (in place, strided) ------------------
__global__ void rope_k(float* __restrict__ x, const int* __restrict__ posIdx,
                       int S, int ld) {
    int gid = blockIdx.x * blockDim.x + threadIdx.x;
    int total = B * S * H * (DH/2);
    if (gid >= total) return;
    int j = gid & 31;
    int h = (gid >> 5) & (H - 1);
    int sb = gid >> 9;
    int s = sb % S;
    int b = sb / S;
    float p = posIdx ? (float)posIdx[b * S + s] : (float)s;
    float inv = powf(10000.f, -(float)j / 32.f);
    float ang = p * inv;
    float c = cosf(ang), sn = sinf(ang);
    size_t base = (size_t)(b * S + s) * ld + h * DH;
    float x1 = x[base + j], x2 = x[base + 32 + j];
    x[base + j]      = x1 * c - x2 * sn;
    x[base + 32 + j] = x2 * c + x1 * sn;
}

// ------------------------------- fused flash attention ---------------------
#define FST 68
__global__ __launch_bounds__(256)
void flash_attn(const float* __restrict__ q, const float* __restrict__ k,
                const float* __restrict__ v, const float* __restrict__ o,
                int S, int ldq)
{
    extern __shared__ float sm[];
    float (*Qs)[FST] = (float(*)[FST])sm;
    float (*Ks)[FST] = (float(*)[FST])(sm + 64*FST);      // reused as Ps
    float (*Vt)[FST] = (float(*)[FST])(sm + 2*64*FST);    // [dh][token]
    __shared__ float redmx[2][64];
    __shared__ float redsm[2][64];

    const int bh = blockIdx.y;
    const int b = bh / H, h = bh % H;
    const int q0 = blockIdx.x * 64;
    const int tid = threadIdx.x, warp = tid >> 5, lane = tid & 31;
    const int gid = lane >> 2, tig = lane & 3;
    const int wm = (warp & 3) * 16;
    const int wn = (warp >> 2) * 32;
    const int warp_n = warp >> 2;

    #pragma unroll
    for (int i = 0; i < 4; i++) {
        int f4 = tid + i * 256;
        int r = f4 >> 4, c = (f4 & 15) << 2;
        float4 qv = *(const float4*)(q + (size_t)(b*S + q0 + r) * ldq + h*DH + c);
        Qs[r][c+0] = f2tf32(qv.x); Qs[r][c+1] = f2tf32(qv.y);
        Qs[r][c+2] = f2tf32(qv.z); Qs[r][c+3] = f2tf32(qv.w);
    }

    float mI[2] = {NEGINF, NEGINF};
    float lI[2] = {0.f, 0.f};
    float oacc[4][4];
    #pragma unroll
    for (int nt = 0; nt < 4; nt++)
        #pragma unroll
        for (int r = 0; r < 4; r++) oacc[nt][r] = 0.f;

    const int numKT = blockIdx.x + 1;
    for (int kt = 0; kt < numKT; kt++) {
        const int k0 = kt * 64;
        __syncthreads();
        #pragma unroll
        for (int i = 0; i < 4; i++) {
            int f4 = tid + i * 256;
            int r = f4 >> 4, c = (f4 & 15) << 2;
            size_t gbase = (size_t)(b*S + k0 + r) * ldq + h*DH + c;
            float4 kv = *(const float4*)(k + gbase);
            Ks[r][c+0] = f2tf32(kv.x); Ks[r][c+1] = f2tf32(kv.y);
            Ks[r][c+2] = f2tf32(kv.z); Ks[r][c+3] = f2tf32(kv.w);
            float4 vv = *(const float4*)(v + gbase);
            Vt[c+0][r] = f2tf32(vv.x); Vt[c+1][r] = f2tf32(vv.y);
            Vt[c+2][r] = f2tf32(vv.z); Vt[c+3][r] = f2tf32(vv.w);
        }
        __syncthreads();

        float sacc[4][4];
        #pragma unroll
        for (int nt = 0; nt < 4; nt++)
            #pragma unroll
            for (int r = 0; r < 4; r++) sacc[nt][r] = 0.f;

        #pragma unroll
        for (int ks = 0; ks < 64; ks += 8) {
            const int kLo = ks + tig, kHi = kLo + 4;
            uint32_t af[4];
            af[0] = __float_as_uint(Qs[wm + gid    ][kLo]);
            af[1] = __float_as_uint(Qs[wm + gid + 8][kLo]);
            af[2] = __float_as_uint(Qs[wm + gid    ][kHi]);
            af[3] = __float_as_uint(Qs[wm + gid + 8][kHi]);
            #pragma unroll
            for (int nt = 0; nt < 4; nt++) {
                uint32_t bf[2];
                bf[0] = __float_as_uint(Ks[wn + nt*8 + gid][kLo]);
                bf[1] = __float_as_uint(Ks[wn + nt*8 + gid][kHi]);
                mma_tf32(sacc[nt], af, bf);
            }
        }

        const float scale = 0.125f;
        const bool diag = (kt == numKT - 1);
        #pragma unroll
        for (int nt = 0; nt < 4; nt++)
            #pragma unroll
            for (int r = 0; r < 4; r++) {
                int rowg = q0 + wm + gid + ((r >> 1) << 3);
                int colg = k0 + wn + nt*8 + tig*2 + (r & 1);
                float sv = sacc[nt][r] * scale;
                sacc[nt][r] = (diag && colg > rowg) ? NEGINF : sv;
            }

        float rmx[2];
        #pragma unroll
        for (int j = 0; j < 2; j++) {
            float m0 = fmaxf(sacc[0][2*j], sacc[0][2*j+1]);
            #pragma unroll
            for (int nt = 1; nt < 4; nt++)
                m0 = fmaxf(m0, fmaxf(sacc[nt][2*j], sacc[nt][2*j+1]));
            m0 = fmaxf(m0, __shfl_xor_sync(0xffffffffu, m0, 1));
            m0 = fmaxf(m0, __shfl_xor_sync(0xffffffffu, m0, 2));
            rmx[j] = m0;
        }
        if (tig == 0) {
            redmx[warp_n][wm + gid    ] = rmx[0];
            redmx[warp_n][wm + gid + 8] = rmx[1];
        }
        __syncthreads();
        rmx[0] = fmaxf(redmx[0][wm + gid    ], redmx[1][wm + gid    ]);
        rmx[1] = fmaxf(redmx[0][wm + gid + 8], redmx[1][wm + gid + 8]);

        float mnew[2], alpha[2];
        #pragma unroll
        for (int j = 0; j < 2; j++) {
            mnew[j] = fmaxf(mI[j], rmx[j]);
            alpha[j] = expf(mI[j] - mnew[j]);
            mI[j] = mnew[j];
        }

        float rsum[2] = {0.f, 0.f};
        #pragma unroll
        for (int nt = 0; nt < 4; nt++)
            #pragma unroll
            for (int r = 0; r < 4; r++) {
                int j = r >> 1;
                float p = expf(sacc[nt][r] - mnew[j]);
                rsum[j] += p;
                Ks[wm + gid + (j << 3)][wn + nt*8 + tig*2 + (r & 1)] = f2tf32(p);
            }
        #pragma unroll
        for (int j = 0; j < 2; j++) {
            rsum[j] += __shfl_xor_sync(0xffffffffu, rsum[j], 1);
            rsum[j] += __shfl_xor_sync(0xffffffffu, rsum[j], 2);
        }
        if (tig == 0) {
            redsm[warp_n][wm + gid    ] = rsum[0];
            redsm[warp_n][wm + gid + 8] = rsum[1];
        }
        __syncthreads();
        rsum[0] = redsm[0][wm + gid    ] + redsm[1][wm + gid    ];
        rsum[1] = redsm[0][wm + gid + 8] + redsm[1][wm + gid + 8];

        #pragma unroll
        for (int j = 0; j < 2; j++) lI[j] = alpha[j] * lI[j] + rsum[j];
        #pragma unroll
        for (int nt = 0; nt < 4; nt++) {
            oacc[nt][0] *= alpha[0]; oacc[nt][1] *= alpha[0];
            oacc[nt][2] *= alpha[1]; oacc[nt][3] *= alpha[1];
        }

        #pragma unroll
        for (int ks = 0; ks < 64; ks += 8) {
            const int kLo = ks + tig, kHi = kLo + 4;
            uint32_t af[4];
            af[0] = __float_as_uint(Ks[wm + gid    ][kLo]);
            af[1] = __float_as_uint(Ks[wm + gid + 8][kLo]);
            af[2] = __float_as_uint(Ks[wm + gid    ][kHi]);
            af[3] = __float_as_uint(Ks[wm + gid + 8][kHi]);
            #pragma unroll
            for (int nt = 0; nt < 4; nt++) {
                uint32_t bf[2];
                bf[0] = __float_as_uint(Vt[wn + nt*8 + gid][kLo]);
                bf[1] = __float_as_uint(Vt[wn + nt*8 + gid][kHi]);
                mma_tf32(oacc[nt], af, bf);
            }
        }
    }

    float inv0 = 1.f / lI[0], inv1 = 1.f / lI[1];
    float* op = (float*)o;
    #pragma unroll
    for (int nt = 0; nt < 4; nt++) {
        int col = h*DH + wn + nt*8 + tig*2;
        size_t r0 = ((size_t)(b*S + q0 + wm + gid)) * (H*DH) + col;
        size_t r1 = ((size_t)(b*S + q0 + wm + gid + 8)) * (H*DH) + col;
        *(float2*)(op + r0) = make_float2(f2tf32(oacc[nt][0]*inv0), f2tf32(oacc[nt][1]*inv0));
        *(float2*)(op + r1) = make_float2(f2tf32(oacc[nt][2]*inv1), f2tf32(oacc[nt][3]*inv1));
    }
}

// ------------------------------- SwiGLU from fused GU buffer ---------------
__global__ void silu_mul_gu(const float* __restrict__ gu, float* __restrict__ out, int n4) {
    int i = blockIdx.x * blockDim.x + threadIdx.x;
    if (i >= n4) return;
    const int cW = FFN / 4;
    int r = i / cW, c = i % cW;
    float4 gv = ((const float4*)gu)[(size_t)r * (2 * cW) + c];
    float4 uv = ((const float4*)gu)[(size_t)r * (2 * cW) + cW + c];
    gv.x = f2tf32(gv.x / (1.f + expf(-gv.x)) * uv.x);
    gv.y = f2tf32(gv.y / (1.f + expf(-gv.y)) * uv.y);
    gv.z = f2tf32(gv.z / (1.f + expf(-gv.z)) * uv.z);
    gv.w = f2tf32(gv.w / (1.f + expf(-gv.w)) * uv.w);
    ((float4*)out)[i] = gv;
}

// ------------------------------- router ------------------------------------
__global__ void router_stats(const float* __restrict__ proc, const float* __restrict__ hid,
                             const float* __restrict__ mulv,
                             float* __restrict__ dst, float* __restrict__ dch)
{
    size_t row = blockIdx.x;
    const float* pr = proc + row * D;
    const float* hi = hid + row * D;
    const float* mu = mulv + row * (2 * D);
    const float* lv = mu + D;
    float s1 = 0.f, s2 = 0.f;
    for (int i = threadIdx.x; i < D; i += 256) {
        float r = pr[i] - hi[i];
        s1 += r * r;
        float l = lv[i];
        float dm = r - mu[i];
        s2 += 0.5f * (l - LOGCF + (CVARF + dm * dm) * expf(-l) - 1.0f);
    }
    s1 = blockReduceSum(s1);
    s2 = blockReduceSum(s2);
    if (threadIdx.x == 0) {
        dst[row] = s1 / (float)D;
        dch[row] = s2 / (float)D;
    }
}

__global__ void router_means(const float* __restrict__ dst, const float* __restrict__ dch,
                             float* __restrict__ means)
{
    float s1 = 0.f, s2 = 0.f;
    for (int i = threadIdx.x; i < B * T; i += 1024) { s1 += dst[i]; s2 += dch[i]; }
    s1 = blockReduceSum(s1);
    s2 = blockReduceSum(s2);
    if (threadIdx.x == 0) {
        means[0] = s1 / (float)(B * T);
        means[1] = s2 / (float)(B * T);
    }
}

__global__ void router_gate(const float* __restrict__ dst, const float* __restrict__ dch,
                            const float* __restrict__ means, float* __restrict__ g)
{
    int i = blockIdx.x * blockDim.x + threadIdx.x;
    if (i >= B * T) return;
    float z = BCE * (dst[i] - means[0]) + BCU * (dch[i] - means[1]);
    g[i] = 1.f / (1.f + expf(-z));
}

__global__ void topk_k(const float* __restrict__ g, int* __restrict__ idxO,
                       float* __restrict__ scO)
{
    int b = blockIdx.x;
    int i = threadIdx.x;
    __shared__ float gs[T];
    __shared__ unsigned char flag[T];
    gs[i] = g[b * T + i];
    __syncthreads();
    float gi = gs[i];
    int rank = 0;
    for (int j = 0; j < T; j++) {
        float gj = gs[j];
        rank += (gj > gi) || (gj == gi && j < i);
    }
    flag[i] = (rank < KSEL) ? 1 : 0;
    __syncthreads();
    if (flag[i]) {
        int pos = 0;
        for (int j = 0; j < i; j++) pos += flag[j];
        idxO[b * KSEL + pos] = i;
        scO[b * KSEL + pos] = gi;
    }
}

// ------------------------------- gather / scatter --------------------------
__global__ void gather_k(const float* __restrict__ proc, const int* __restrict__ idx,
                         float* __restrict__ sel)
{
    int row = blockIdx.x;
    int b = row / KSEL;
    int src = idx[row];
    const float4* s4 = (const float4*)(proc + ((size_t)b * T + src) * D);
    float4* d4 = (float4*)(sel + (size_t)row * D);
    d4[threadIdx.x] = s4[threadIdx.x];
}

__global__ void scatter_k(const float* __restrict__ sel, const float* __restrict__ y,
                          const float* __restrict__ sc, const int* __restrict__ idx,
                          float* __restrict__ out)
{
    int row = blockIdx.x;
    int b = row / KSEL;
    float s = sc[row];
    size_t drow = ((size_t)b * T + idx[row]) * D;
    const float4* s4 = (const float4*)(sel + (size_t)row * D);
    const float4* y4 = (const float4*)(y + (size_t)row * D);
    float4 sv = s4[threadIdx.x];
    float4 yv = y4[threadIdx.x];
    float4 ov = make_float4(sv.x + s * (yv.x - sv.x),
                            sv.y + s * (yv.y - sv.y),
                            sv.z + s * (yv.z - sv.z),
                            sv.w + s * (yv.w - sv.w));
    ((float4*)(out + drow))[threadIdx.x] = ov;
}

// ------------------------------- host: decoder pipeline --------------------
#define FLASH_SMEM (3 * 64 * FST * 4)

static void run_decoder(const float* x_in, int S, const int* posIdx,
                        const float* ln1, const float* wq, const float* wk,
                        const float* wv, const float* wo, const float* ln2,
                        const float* wg, const float* wu, const float* wd,
                        float* out,
                        float* h, float* qkv, float* attn,
                        float* x, float* ffgu, float* ffg)
{
    const int M = B * S;
    rmsnorm_k<<<M, 256>>>(x_in, ln1, h);
    launch_gemm3(h, wq, wk, wv, nullptr, qkv, M, 3 * D, D, D);
    int ropeTotal = B * S * H * (DH / 2);
    rope_k<<<(ropeTotal + 255) / 256, 256>>>(qkv,     posIdx, S, 3 * D);  // q part
    rope_k<<<(ropeTotal + 255) / 256, 256>>>(qkv + D, posIdx, S, 3 * D);  // k part
    flash_attn<<<dim3(S / 64, B * H), 256, FLASH_SMEM>>>(qkv, qkv + D, qkv + 2 * D,
                                                         attn, S, 3 * D);
    launch_gemm3(attn, wo, wo, wo, x_in, x, M, D, D, D);
    rmsnorm_k<<<M, 256>>>(x, ln2, h);
    launch_gemm3(h, wg, wu, wu, nullptr, ffgu, M, 2 * FFN, D, FFN);
    int n4 = M * FFN / 4;
    silu_mul_gu<<<(n4 + 255) / 256, 256>>>(ffgu, ffg, n4);
    launch_gemm3(ffg, wd, wd, wd, x, out, M, D, FFN, D);
}

// ------------------------------- entry -------------------------------------
extern "C" void kernel_launch(void* const* d_in, const int* in_sizes, int n_in,
                              void* d_out, int out_size)
{
    if (n_in < 21) return;
    const float* in[21];
    for (int i = 0; i < 21; i++) in[i] = (const float*)d_in[i];

    const float *hidden, *ln1_1, *wq1, *wk1, *wv1, *wo1, *ln2_1, *wg1, *wu1, *wd1;
    const float *ln1_2, *wq2, *wk2, *wv2, *wo2, *ln2_2, *wg2, *wu2, *wd2, *pnw, *pw;

    if (in_sizes[1] == D) {
        hidden = in[0];  ln1_1 = in[1];  wq1 = in[2];  wk1 = in[3];  wv1 = in[4];
        wo1 = in[5];     ln2_1 = in[6];  wg1 = in[7];  wu1 = in[8];  wd1 = in[9];
        ln1_2 = in[10];  wq2 = in[11];   wk2 = in[12]; wv2 = in[13]; wo2 = in[14];
        ln2_2 = in[15];  wg2 = in[16];   wu2 = in[17]; wd2 = in[18];
        pnw = in[19];    pw = in[20];
    } else {
        hidden = in[0];
        wq1 = in[1];  wk1 = in[2];  wv1 = in[3];  wo1 = in[4];
        wq2 = in[5];  wk2 = in[6];  wv2 = in[7];  wo2 = in[8];
        wg1 = in[9];  wu1 = in[10]; wd1 = in[11];
        wg2 = in[12]; wu2 = in[13]; wd2 = in[14];
        ln1_1 = in[15]; ln2_1 = in[16]; ln1_2 = in[17]; ln2_2 = in[18];
        pnw = in[19]; pw = in[20];
    }

    cudaFuncSetAttribute(flash_attn, cudaFuncAttributeMaxDynamicSharedMemorySize,
                         FLASH_SMEM);

    float *h, *qkv, *attn, *x, *ffgu, *ffg, *mulv;
    float *dst, *dch, *gate, *means, *sc, *sel, *y;
    int* idx;
    cudaGetSymbolAddress((void**)&h, g_h);
    cudaGetSymbolAddress((void**)&qkv, g_qkv);
    cudaGetSymbolAddress((void**)&attn, g_attn);
    cudaGetSymbolAddress((void**)&x, g_x);
    cudaGetSymbolAddress((void**)&ffgu, g_ffgu);
    cudaGetSymbolAddress((void**)&ffg, g_ffg);
    cudaGetSymbolAddress((void**)&mulv, g_mulv);
    cudaGetSymbolAddress((void**)&dst, g_dst);
    cudaGetSymbolAddress((void**)&dch, g_dch);
    cudaGetSymbolAddress((void**)&gate, g_gate);
    cudaGetSymbolAddress((void**)&means, g_means);
    cudaGetSymbolAddress((void**)&idx, g_idx);
    cudaGetSymbolAddress((void**)&sc, g_sc);
    cudaGetSymbolAddress((void**)&sel, g_sel);
    cudaGetSymbolAddress((void**)&y, g_y);

    float* proc = (float*)d_out;   // decoder1 writes the output buffer directly

    // decoder 1: hidden -> proc (= d_out)
    run_decoder(hidden, T, nullptr,
                ln1_1, wq1, wk1, wv1, wo1, ln2_1, wg1, wu1, wd1,
                proc, h, qkv, attn, x, ffgu, ffg);

    // router
    rmsnorm_k<<<B * T, 256>>>(hidden, pnw, h);
    launch_gemm3(h, pw, pw, pw, nullptr, mulv, B * T, 2 * D, D, 2 * D);
    router_stats<<<B * T, 256>>>(proc, hidden, mulv, dst, dch);
    router_means<<<1, 1024>>>(dst, dch, means);
    router_gate<<<(B * T + 255) / 256, 256>>>(dst, dch, means, gate);
    topk_k<<<B, 1024>>>(gate, idx, sc);
    gather_k<<<B * KSEL, 256>>>(proc, idx, sel);

    // decoder 2 on selected tokens: sel -> y
    run_decoder(sel, KSEL, idx,
                ln1_2, wq2, wk2, wv2, wo2, ln2_2, wg2, wu2, wd2,
                y, h, qkv, attn, x, ffgu, ffg);

    // out[b, idx] = sel + sc*(y - sel)   (rest of d_out already = proc)
    scatter_k<<<B * KSEL, 256>>>(sel, y, sc, idx, (float*)d_out);
}